// round 1
// baseline (speedup 1.0000x reference)
#include <cuda_runtime.h>
#include <cuda_bf16.h>

// Problem constants (from reference): N=100000 nodes, E=1.6M edges, D=128.
#define NMAX 100000
#define EMAX 1600000
#define D 128
#define SCAN_B 1024

// ---------------- scratch (static device globals; no runtime allocation) ----------
__device__ int   g_deg_out[NMAX];
__device__ int   g_deg_in [NMAX];
__device__ float g_inv_out[NMAX];
__device__ float g_inv_in [NMAX];
__device__ int   g_row_off[NMAX + 1];
__device__ int   g_cursor [NMAX];
__device__ int   g_csr    [EMAX];
__device__ int   g_bsum   [256];
__device__ int   g_boff   [257];
__device__ float g_h      [(size_t)NMAX * D];
__device__ float g_h2     [(size_t)NMAX * D];
__device__ float g_t      [(size_t)NMAX * D];
__device__ float g_colsum [D];

// ---------------- setup kernels ---------------------------------------------------
__global__ void k_zero(int n) {
    int i = blockIdx.x * blockDim.x + threadIdx.x;
    if (i < n) { g_deg_out[i] = 0; g_deg_in[i] = 0; g_cursor[i] = 0; }
    if (i < D) g_colsum[i] = 0.0f;
}

__global__ void k_deg(const int* __restrict__ src, const int* __restrict__ dst, int e) {
    int i = blockIdx.x * blockDim.x + threadIdx.x;
    if (i < e) {
        atomicAdd(&g_deg_out[src[i]], 1);
        atomicAdd(&g_deg_in [dst[i]], 1);
    }
}

__global__ void k_inv(int n) {
    int i = blockIdx.x * blockDim.x + threadIdx.x;
    if (i < n) {
        g_inv_out[i] = rsqrtf((float)max(g_deg_out[i], 1));
        g_inv_in [i] = rsqrtf((float)max(g_deg_in [i], 1));
    }
}

// inclusive scan of deg_in per 1024-block; row_off[i+1] = incl; bsum[b] = block total
__global__ void k_scan1(int n) {
    __shared__ int s[SCAN_B];
    int t = threadIdx.x;
    int i = blockIdx.x * SCAN_B + t;
    int v = (i < n) ? g_deg_in[i] : 0;
    s[t] = v;
    __syncthreads();
    for (int off = 1; off < SCAN_B; off <<= 1) {
        int x = 0;
        if (t >= off) x = s[t - off];
        __syncthreads();
        s[t] += x;
        __syncthreads();
    }
    if (i < n) g_row_off[i + 1] = s[t];
    if (t == SCAN_B - 1) g_bsum[blockIdx.x] = s[t];
}

__global__ void k_scan2(int nb) {  // single thread: exclusive scan of block sums
    if (threadIdx.x == 0 && blockIdx.x == 0) {
        int acc = 0;
        for (int i = 0; i < nb; i++) { g_boff[i] = acc; acc += g_bsum[i]; }
        g_boff[nb] = acc;
    }
}

__global__ void k_scan3(int n) {
    int t = threadIdx.x;
    int i = blockIdx.x * SCAN_B + t;
    if (i < n) g_row_off[i + 1] += g_boff[blockIdx.x];
    if (i == 0) g_row_off[0] = 0;
}

__global__ void k_fill(const int* __restrict__ src, const int* __restrict__ dst, int e) {
    int i = blockIdx.x * blockDim.x + threadIdx.x;
    if (i < e) {
        int d = dst[i];
        int p = g_row_off[d] + atomicAdd(&g_cursor[d], 1);
        g_csr[p] = src[i];
    }
}

// ---------------- GEMM: t[r,:] = (h[r,:] * inv_out[r]) @ W  ------------------------
// Block: 64 rows x 128 cols, 256 threads, each thread 8 rows x 4 cols.
// Full W (128x128 fp32 = 64KB) in dynamic shared + 64x16 H tile.
#define GEMM_BM 64
#define GEMM_SMEM (128 * 128 * 4 + GEMM_BM * 16 * 4)

__global__ void __launch_bounds__(256, 3)
k_gemm(const float* __restrict__ hin, const float* __restrict__ W,
       float* __restrict__ tout, int n) {
    extern __shared__ float sm[];
    float* Ws = sm;                 // [k][c] 128x128
    float* Hs = sm + 128 * 128;     // [row][k] 64x16

    int tid = threadIdx.x;

    // load full W
    const float4* W4 = (const float4*)W;
    float4* Ws4 = (float4*)Ws;
    #pragma unroll
    for (int i = tid; i < 128 * 128 / 4; i += 256) Ws4[i] = W4[i];

    int row0 = blockIdx.x * GEMM_BM;
    int c0   = (tid & 31) * 4;      // column start (float4)
    int rgrp = tid >> 5;            // 0..7 -> rows row0 + rgrp*8 + rr

    float acc[8][4];
    #pragma unroll
    for (int rr = 0; rr < 8; rr++)
        #pragma unroll
        for (int j = 0; j < 4; j++) acc[rr][j] = 0.0f;

    __syncthreads();

    for (int k0 = 0; k0 < 128; k0 += 16) {
        __syncthreads();
        // load scaled H tile: 64 rows x 16 k = 256 float4, 1 per thread
        {
            int i  = tid;
            int r  = i >> 2;
            int kk = (i & 3) * 4;
            int gr = row0 + r;
            float4 v = make_float4(0.f, 0.f, 0.f, 0.f);
            if (gr < n) {
                v = *(const float4*)&hin[(size_t)gr * D + k0 + kk];
                float s = g_inv_out[gr];
                v.x *= s; v.y *= s; v.z *= s; v.w *= s;
            }
            *(float4*)&Hs[r * 16 + kk] = v;
        }
        __syncthreads();

        #pragma unroll
        for (int kk = 0; kk < 16; kk++) {
            float4 w = *(const float4*)&Ws[(k0 + kk) * 128 + c0];
            #pragma unroll
            for (int rr = 0; rr < 8; rr++) {
                float hv = Hs[(rgrp * 8 + rr) * 16 + kk];  // warp-uniform broadcast
                acc[rr][0] = fmaf(hv, w.x, acc[rr][0]);
                acc[rr][1] = fmaf(hv, w.y, acc[rr][1]);
                acc[rr][2] = fmaf(hv, w.z, acc[rr][2]);
                acc[rr][3] = fmaf(hv, w.w, acc[rr][3]);
            }
        }
    }

    #pragma unroll
    for (int rr = 0; rr < 8; rr++) {
        int gr = row0 + rgrp * 8 + rr;
        if (gr < n) {
            float4 o = make_float4(acc[rr][0], acc[rr][1], acc[rr][2], acc[rr][3]);
            *(float4*)&tout[(size_t)gr * D + c0] = o;
        }
    }
}

// ---------------- aggregation: hout[n,:] = relu(inv_in[n] * sum_{e in CSR[n]} t[src_e,:] + b)
// one warp per node, lane handles 4 contiguous cols (float4), 4-edge unrolled for MLP
__global__ void __launch_bounds__(256)
k_agg(const float* __restrict__ tin, const float* __restrict__ b,
      float* __restrict__ hout, int n) {
    int warp = (blockIdx.x * blockDim.x + threadIdx.x) >> 5;
    int lane = threadIdx.x & 31;
    if (warp >= n) return;

    int s = g_row_off[warp];
    int e = g_row_off[warp + 1];
    int coff = lane * 4;

    float ax = 0.f, ay = 0.f, az = 0.f, aw = 0.f;
    int i = s;
    for (; i + 4 <= e; i += 4) {
        int s0 = g_csr[i], s1 = g_csr[i + 1], s2 = g_csr[i + 2], s3 = g_csr[i + 3];
        float4 v0 = *(const float4*)&tin[(size_t)s0 * D + coff];
        float4 v1 = *(const float4*)&tin[(size_t)s1 * D + coff];
        float4 v2 = *(const float4*)&tin[(size_t)s2 * D + coff];
        float4 v3 = *(const float4*)&tin[(size_t)s3 * D + coff];
        ax += (v0.x + v1.x) + (v2.x + v3.x);
        ay += (v0.y + v1.y) + (v2.y + v3.y);
        az += (v0.z + v1.z) + (v2.z + v3.z);
        aw += (v0.w + v1.w) + (v2.w + v3.w);
    }
    for (; i < e; i++) {
        int s0 = g_csr[i];
        float4 v0 = *(const float4*)&tin[(size_t)s0 * D + coff];
        ax += v0.x; ay += v0.y; az += v0.z; aw += v0.w;
    }

    float inv = g_inv_in[warp];
    float4 bb = *(const float4*)&b[coff];
    float4 o;
    o.x = fmaxf(fmaf(ax, inv, bb.x), 0.f);
    o.y = fmaxf(fmaf(ay, inv, bb.y), 0.f);
    o.z = fmaxf(fmaf(az, inv, bb.z), 0.f);
    o.w = fmaxf(fmaf(aw, inv, bb.w), 0.f);
    *(float4*)&hout[(size_t)warp * D + coff] = o;
}

// ---------------- epilogue: column mean + MLP -------------------------------------
__global__ void k_colsum(const float* __restrict__ h, int n) {
    int c = threadIdx.x;  // 128 threads
    int rows_per = (n + gridDim.x - 1) / gridDim.x;
    int r0 = blockIdx.x * rows_per;
    int r1 = min(n, r0 + rows_per);
    float acc = 0.f;
    for (int r = r0; r < r1; r++) acc += h[(size_t)r * D + c];
    atomicAdd(&g_colsum[c], acc);
}

__global__ void k_mlp(const float* __restrict__ Wl1, const float* __restrict__ bl1,
                      const float* __restrict__ Wl2, const float* __restrict__ bl2,
                      const float* __restrict__ Wo,  const float* __restrict__ bo,
                      float* __restrict__ out, int n) {
    __shared__ float s0[D], s1[D], s2[D];
    int t = threadIdx.x;  // 128 threads
    s0[t] = g_colsum[t] * (1.0f / (float)n);
    __syncthreads();

    float a = bl1[t];
    for (int k = 0; k < D; k++) a = fmaf(s0[k], Wl1[k * D + t], a);
    s1[t] = fmaxf(a, 0.f);
    __syncthreads();

    float a2 = bl2[t];
    for (int k = 0; k < D; k++) a2 = fmaf(s1[k], Wl2[k * D + t], a2);
    s2[t] = fmaxf(a2, 0.f) * Wo[t];
    __syncthreads();

    for (int off = 64; off > 0; off >>= 1) {
        if (t < off) s2[t] += s2[t + off];
        __syncthreads();
    }
    if (t == 0) out[0] = s2[0] + bo[0];
}

// ---------------- launch ----------------------------------------------------------
extern "C" void kernel_launch(void* const* d_in, const int* in_sizes, int n_in,
                              void* d_out, int out_size) {
    const float* x   = (const float*)d_in[0];
    const int*   src = (const int*)  d_in[1];
    const int*   dst = (const int*)  d_in[2];
    const float* W1  = (const float*)d_in[3];
    const float* b1  = (const float*)d_in[4];
    const float* W2  = (const float*)d_in[5];
    const float* b2  = (const float*)d_in[6];
    const float* W3  = (const float*)d_in[7];
    const float* b3  = (const float*)d_in[8];
    const float* W4  = (const float*)d_in[9];
    const float* b4  = (const float*)d_in[10];
    const float* Wl1 = (const float*)d_in[11];
    const float* bl1 = (const float*)d_in[12];
    const float* Wl2 = (const float*)d_in[13];
    const float* bl2 = (const float*)d_in[14];
    const float* Wo  = (const float*)d_in[15];
    const float* bo  = (const float*)d_in[16];
    float* out = (float*)d_out;

    int n = in_sizes[0] / D;
    int e = in_sizes[1];

    cudaFuncSetAttribute(k_gemm, cudaFuncAttributeMaxDynamicSharedMemorySize, GEMM_SMEM);

    float *h, *h2, *t;
    cudaGetSymbolAddress((void**)&h,  g_h);
    cudaGetSymbolAddress((void**)&h2, g_h2);
    cudaGetSymbolAddress((void**)&t,  g_t);

    int nb = (n + SCAN_B - 1) / SCAN_B;

    k_zero <<<(n + 255) / 256, 256>>>(n);
    k_deg  <<<(e + 255) / 256, 256>>>(src, dst, e);
    k_inv  <<<(n + 255) / 256, 256>>>(n);
    k_scan1<<<nb, SCAN_B>>>(n);
    k_scan2<<<1, 1>>>(nb);
    k_scan3<<<nb, SCAN_B>>>(n);
    k_fill <<<(e + 255) / 256, 256>>>(src, dst, e);

    int gemm_grid = (n + GEMM_BM - 1) / GEMM_BM;
    int agg_grid  = (n * 32 + 255) / 256;

    // layer 1: x -> h
    k_gemm<<<gemm_grid, 256, GEMM_SMEM>>>(x, W1, t, n);
    k_agg <<<agg_grid, 256>>>(t, b1, h, n);
    // layer 2: h -> h2
    k_gemm<<<gemm_grid, 256, GEMM_SMEM>>>(h, W2, t, n);
    k_agg <<<agg_grid, 256>>>(t, b2, h2, n);
    // layer 3: h2 -> h
    k_gemm<<<gemm_grid, 256, GEMM_SMEM>>>(h2, W3, t, n);
    k_agg <<<agg_grid, 256>>>(t, b3, h, n);
    // layer 4: h -> h2
    k_gemm<<<gemm_grid, 256, GEMM_SMEM>>>(h, W4, t, n);
    k_agg <<<agg_grid, 256>>>(t, b4, h2, n);

    k_colsum<<<240, D>>>(h2, n);
    k_mlp<<<1, D>>>(Wl1, bl1, Wl2, bl2, Wo, bo, out, n);
}

// round 5
// speedup vs baseline: 1.2087x; 1.2087x over previous
#include <cuda_runtime.h>
#include <cuda_bf16.h>
#include <cstdint>

// Problem constants: N=100000 nodes, E=1.6M edges, D=128.
#define NMAX 100000
#define EMAX 1600000
#define D 128
#define SCAN_B 1024

// ================= scratch (static device globals) ================================
__device__ int   g_deg_out[NMAX];
__device__ int   g_deg_in [NMAX];
__device__ float g_inv_out[NMAX];
__device__ float g_inv_in [NMAX];
__device__ int   g_row_off[NMAX + 1];
__device__ int   g_cursor [NMAX];
__device__ int   g_csr    [EMAX];
__device__ int   g_bsum   [256];
__device__ int   g_boff   [257];
__device__ float g_h      [(size_t)NMAX * D];
__device__ float g_h2     [(size_t)NMAX * D];
__device__ float g_t      [(size_t)NMAX * D];
__device__ float g_colsum [D];
// W fragments per layer: [kit(16)][nt2(8)][lane(32)] x float4 = 16384 floats / layer
__device__ float g_wfrag  [4 * 16384];

// tf32 round-to-nearest; cvt.rna.tf32.f32 requires b32 destination
__device__ __forceinline__ float to_tf32(float x) {
    uint32_t r;
    asm("cvt.rna.tf32.f32 %0, %1;" : "=r"(r) : "f"(x));
    return __uint_as_float(r);
}

// m16n8k8 tf32 MMA, fp32 accumulate in place
__device__ __forceinline__ void mma_tf32(float* c, uint32_t a0, uint32_t a1,
                                         uint32_t a2, uint32_t a3,
                                         uint32_t b0, uint32_t b1) {
    asm volatile(
        "mma.sync.aligned.m16n8k8.row.col.f32.tf32.tf32.f32 "
        "{%0,%1,%2,%3}, {%4,%5,%6,%7}, {%8,%9}, {%0,%1,%2,%3};"
        : "+f"(c[0]), "+f"(c[1]), "+f"(c[2]), "+f"(c[3])
        : "r"(a0), "r"(a1), "r"(a2), "r"(a3), "r"(b0), "r"(b1));
}

// ================= setup kernels ==================================================
__global__ void k_zero(int n) {
    int i = blockIdx.x * blockDim.x + threadIdx.x;
    if (i < n) { g_deg_out[i] = 0; g_deg_in[i] = 0; g_cursor[i] = 0; }
    if (i < D) g_colsum[i] = 0.0f;
}

__global__ void k_deg(const int* __restrict__ src, const int* __restrict__ dst, int e) {
    int i = blockIdx.x * blockDim.x + threadIdx.x;
    if (i < e) {
        atomicAdd(&g_deg_out[src[i]], 1);
        atomicAdd(&g_deg_in [dst[i]], 1);
    }
}

__global__ void k_inv(int n) {
    int i = blockIdx.x * blockDim.x + threadIdx.x;
    if (i < n) {
        g_inv_out[i] = rsqrtf((float)max(g_deg_out[i], 1));
        g_inv_in [i] = rsqrtf((float)max(g_deg_in [i], 1));
    }
}

__global__ void k_scan1(int n) {
    __shared__ int s[SCAN_B];
    int t = threadIdx.x;
    int i = blockIdx.x * SCAN_B + t;
    int v = (i < n) ? g_deg_in[i] : 0;
    s[t] = v;
    __syncthreads();
    for (int off = 1; off < SCAN_B; off <<= 1) {
        int x = 0;
        if (t >= off) x = s[t - off];
        __syncthreads();
        s[t] += x;
        __syncthreads();
    }
    if (i < n) g_row_off[i + 1] = s[t];
    if (t == SCAN_B - 1) g_bsum[blockIdx.x] = s[t];
}

__global__ void k_scan2(int nb) {
    if (threadIdx.x == 0 && blockIdx.x == 0) {
        int acc = 0;
        for (int i = 0; i < nb; i++) { g_boff[i] = acc; acc += g_bsum[i]; }
        g_boff[nb] = acc;
    }
}

__global__ void k_scan3(int n) {
    int t = threadIdx.x;
    int i = blockIdx.x * SCAN_B + t;
    if (i < n) g_row_off[i + 1] += g_boff[blockIdx.x];
    if (i == 0) g_row_off[0] = 0;
}

__global__ void k_fill(const int* __restrict__ src, const int* __restrict__ dst, int e) {
    int i = blockIdx.x * blockDim.x + threadIdx.x;
    if (i < e) {
        int d = dst[i];
        int p = g_row_off[d] + atomicAdd(&g_cursor[d], 1);
        g_csr[p] = src[i];
    }
}

// Pack W (128x128 row-major, [k][n]) into mma fragment-major layout per layer:
// float4 at [(kit*8 + nt2)*32 + lane] = { b0(nt=2*nt2), b1(nt), b0(nt+1), b1(nt+1) }
// where b0 = W[kit*8 + lane%4][n0 + lane/4], b1 = W[kit*8+4+lane%4][n0 + lane/4].
__global__ void k_wfrag(const float* __restrict__ W1, const float* __restrict__ W2,
                        const float* __restrict__ W3, const float* __restrict__ W4) {
    const float* W = (blockIdx.x == 0) ? W1 : (blockIdx.x == 1) ? W2
                   : (blockIdx.x == 2) ? W3 : W4;
    float4* out = (float4*)&g_wfrag[(size_t)blockIdx.x * 16384];
    for (int i = threadIdx.x; i < 4096; i += blockDim.x) {
        int lane = i & 31;
        int nt2  = (i >> 5) & 7;
        int kit  = i >> 8;
        int kk = kit * 8 + (lane & 3);
        int c0 = nt2 * 16 + (lane >> 2);
        float4 v;
        v.x = to_tf32(W[kk * D + c0]);
        v.y = to_tf32(W[(kk + 4) * D + c0]);
        v.z = to_tf32(W[kk * D + c0 + 8]);
        v.w = to_tf32(W[(kk + 4) * D + c0 + 8]);
        out[i] = v;
    }
}

// ================= tensor-core GEMM: t = (diag(inv_out) * hin) @ W ================
// mma.sync m16n8k8 tf32. CTA tile 128x128, 8 warps, warp tile 32x64.
// Shared: W-frags 64KB (loaded once per persistent CTA) + A chunk 128x32 (pad 36).
#define GM_SW_F4 4096                 // float4 count of W-frag buffer
#define GM_SA_OFF (GM_SW_F4 * 16)     // byte offset of A buffer
#define GM_SMEM (GM_SA_OFF + 128 * 36 * 4)   // 65536 + 18432 = 83968 B

__global__ void __launch_bounds__(256, 2)
k_gemm_mma(const float* __restrict__ hin, const float* __restrict__ wfrag,
           float* __restrict__ tout, int n, int ntiles) {
    extern __shared__ char smem[];
    float4* sW = (float4*)smem;
    float*  sA = (float*)(smem + GM_SA_OFF);

    int tid = threadIdx.x;
    int w = tid >> 5, lane = tid & 31;
    int qr = lane >> 2;        // 0..7
    int qc = lane & 3;         // 0..3
    int mrow = (w & 3) * 32;   // warp row base within tile
    int nc2_0 = (w >> 2) * 4;  // warp nt2 base (cols (w>>2)*64)
    int ncol = (w >> 2) * 64;

    // stage W fragments once
    const float4* wf4 = (const float4*)wfrag;
    for (int i = tid; i < GM_SW_F4; i += 256) sW[i] = wf4[i];
    // (first __syncthreads inside the kc loop covers this)

    for (int tile = blockIdx.x; tile < ntiles; tile += gridDim.x) {
        int row0 = tile * 128;
        float acc[2][8][4];
        #pragma unroll
        for (int s = 0; s < 2; s++)
            #pragma unroll
            for (int nt = 0; nt < 8; nt++)
                #pragma unroll
                for (int j = 0; j < 4; j++) acc[s][nt][j] = 0.0f;

        #pragma unroll
        for (int kc = 0; kc < 4; kc++) {
            __syncthreads();   // prior chunk's reads done (also fences sW load)
            // stage A chunk: 128 rows x 32 cols, scaled + tf32-rounded
            for (int i = tid; i < 1024; i += 256) {
                int r  = i >> 3;
                int c4 = (i & 7) * 4;
                int gr = row0 + r;
                float4 v = make_float4(0.f, 0.f, 0.f, 0.f);
                if (gr < n) {
                    v = *(const float4*)&hin[(size_t)gr * D + kc * 32 + c4];
                    float s = g_inv_out[gr];
                    v.x = to_tf32(v.x * s); v.y = to_tf32(v.y * s);
                    v.z = to_tf32(v.z * s); v.w = to_tf32(v.w * s);
                }
                *(float4*)&sA[r * 36 + c4] = v;
            }
            __syncthreads();

            #pragma unroll
            for (int kit = 0; kit < 4; kit++) {
                int kitg = kc * 4 + kit;
                // A fragments: j = slab*2 + half; row = mrow + slab*16 + half*8 + qr
                uint32_t a[4][2];
                #pragma unroll
                for (int j = 0; j < 4; j++) {
                    int r = mrow + ((j >> 1) << 4) + ((j & 1) << 3) + qr;
                    a[j][0] = __float_as_uint(sA[r * 36 + kit * 8 + qc]);
                    a[j][1] = __float_as_uint(sA[r * 36 + kit * 8 + 4 + qc]);
                }
                #pragma unroll
                for (int i = 0; i < 4; i++) {
                    float4 bb = sW[(kitg * 8 + nc2_0 + i) * 32 + lane];
                    uint32_t b0a = __float_as_uint(bb.x), b1a = __float_as_uint(bb.y);
                    uint32_t b0b = __float_as_uint(bb.z), b1b = __float_as_uint(bb.w);
                    #pragma unroll
                    for (int s = 0; s < 2; s++) {
                        mma_tf32(acc[s][2 * i],
                                 a[s * 2][0], a[s * 2 + 1][0],
                                 a[s * 2][1], a[s * 2 + 1][1], b0a, b1a);
                        mma_tf32(acc[s][2 * i + 1],
                                 a[s * 2][0], a[s * 2 + 1][0],
                                 a[s * 2][1], a[s * 2 + 1][1], b0b, b1b);
                    }
                }
            }
        }

        // epilogue: c0/c1 -> (row, col..col+1), c2/c3 -> (row+8, ..)
        #pragma unroll
        for (int s = 0; s < 2; s++) {
            int r0g = row0 + mrow + s * 16 + qr;
            int r1g = r0g + 8;
            #pragma unroll
            for (int nt = 0; nt < 8; nt++) {
                int col = ncol + nt * 8 + qc * 2;
                if (r0g < n) {
                    float2 o = make_float2(acc[s][nt][0], acc[s][nt][1]);
                    *(float2*)&tout[(size_t)r0g * D + col] = o;
                }
                if (r1g < n) {
                    float2 o = make_float2(acc[s][nt][2], acc[s][nt][3]);
                    *(float2*)&tout[(size_t)r1g * D + col] = o;
                }
            }
        }
    }
}

// ================= aggregation ====================================================
__global__ void __launch_bounds__(256)
k_agg(const float* __restrict__ tin, const float* __restrict__ b,
      float* __restrict__ hout, int n) {
    int warp = (blockIdx.x * blockDim.x + threadIdx.x) >> 5;
    int lane = threadIdx.x & 31;
    if (warp >= n) return;

    int s = g_row_off[warp];
    int e = g_row_off[warp + 1];
    int coff = lane * 4;

    float ax = 0.f, ay = 0.f, az = 0.f, aw = 0.f;
    int i = s;
    for (; i + 4 <= e; i += 4) {
        int s0 = g_csr[i], s1 = g_csr[i + 1], s2 = g_csr[i + 2], s3 = g_csr[i + 3];
        float4 v0 = *(const float4*)&tin[(size_t)s0 * D + coff];
        float4 v1 = *(const float4*)&tin[(size_t)s1 * D + coff];
        float4 v2 = *(const float4*)&tin[(size_t)s2 * D + coff];
        float4 v3 = *(const float4*)&tin[(size_t)s3 * D + coff];
        ax += (v0.x + v1.x) + (v2.x + v3.x);
        ay += (v0.y + v1.y) + (v2.y + v3.y);
        az += (v0.z + v1.z) + (v2.z + v3.z);
        aw += (v0.w + v1.w) + (v2.w + v3.w);
    }
    for (; i < e; i++) {
        int s0 = g_csr[i];
        float4 v0 = *(const float4*)&tin[(size_t)s0 * D + coff];
        ax += v0.x; ay += v0.y; az += v0.z; aw += v0.w;
    }

    float inv = g_inv_in[warp];
    float4 bb = *(const float4*)&b[coff];
    float4 o;
    o.x = fmaxf(fmaf(ax, inv, bb.x), 0.f);
    o.y = fmaxf(fmaf(ay, inv, bb.y), 0.f);
    o.z = fmaxf(fmaf(az, inv, bb.z), 0.f);
    o.w = fmaxf(fmaf(aw, inv, bb.w), 0.f);
    *(float4*)&hout[(size_t)warp * D + coff] = o;
}

// ================= epilogue =======================================================
__global__ void k_colsum(const float* __restrict__ h, int n) {
    int c = threadIdx.x;
    int rows_per = (n + gridDim.x - 1) / gridDim.x;
    int r0 = blockIdx.x * rows_per;
    int r1 = min(n, r0 + rows_per);
    float acc = 0.f;
    for (int r = r0; r < r1; r++) acc += h[(size_t)r * D + c];
    atomicAdd(&g_colsum[c], acc);
}

__global__ void k_mlp(const float* __restrict__ Wl1, const float* __restrict__ bl1,
                      const float* __restrict__ Wl2, const float* __restrict__ bl2,
                      const float* __restrict__ Wo,  const float* __restrict__ bo,
                      float* __restrict__ out, int n) {
    __shared__ float s0[D], s1[D], s2[D];
    int t = threadIdx.x;
    s0[t] = g_colsum[t] * (1.0f / (float)n);
    __syncthreads();

    float a = bl1[t];
    for (int k = 0; k < D; k++) a = fmaf(s0[k], Wl1[k * D + t], a);
    s1[t] = fmaxf(a, 0.f);
    __syncthreads();

    float a2 = bl2[t];
    for (int k = 0; k < D; k++) a2 = fmaf(s1[k], Wl2[k * D + t], a2);
    s2[t] = fmaxf(a2, 0.f) * Wo[t];
    __syncthreads();

    for (int off = 64; off > 0; off >>= 1) {
        if (t < off) s2[t] += s2[t + off];
        __syncthreads();
    }
    if (t == 0) out[0] = s2[0] + bo[0];
}

// ================= launch =========================================================
extern "C" void kernel_launch(void* const* d_in, const int* in_sizes, int n_in,
                              void* d_out, int out_size) {
    const float* x   = (const float*)d_in[0];
    const int*   src = (const int*)  d_in[1];
    const int*   dst = (const int*)  d_in[2];
    const float* W1  = (const float*)d_in[3];
    const float* b1  = (const float*)d_in[4];
    const float* W2  = (const float*)d_in[5];
    const float* b2  = (const float*)d_in[6];
    const float* W3  = (const float*)d_in[7];
    const float* b3  = (const float*)d_in[8];
    const float* W4  = (const float*)d_in[9];
    const float* b4  = (const float*)d_in[10];
    const float* Wl1 = (const float*)d_in[11];
    const float* bl1 = (const float*)d_in[12];
    const float* Wl2 = (const float*)d_in[13];
    const float* bl2 = (const float*)d_in[14];
    const float* Wo  = (const float*)d_in[15];
    const float* bo  = (const float*)d_in[16];
    float* out = (float*)d_out;

    int n = in_sizes[0] / D;
    int e = in_sizes[1];

    cudaFuncSetAttribute(k_gemm_mma, cudaFuncAttributeMaxDynamicSharedMemorySize,
                         GM_SMEM);

    float *h, *h2, *t, *wf;
    cudaGetSymbolAddress((void**)&h,  g_h);
    cudaGetSymbolAddress((void**)&h2, g_h2);
    cudaGetSymbolAddress((void**)&t,  g_t);
    cudaGetSymbolAddress((void**)&wf, g_wfrag);

    int nb = (n + SCAN_B - 1) / SCAN_B;

    k_zero <<<(n + 255) / 256, 256>>>(n);
    k_deg  <<<(e + 255) / 256, 256>>>(src, dst, e);
    k_inv  <<<(n + 255) / 256, 256>>>(n);
    k_scan1<<<nb, SCAN_B>>>(n);
    k_scan2<<<1, 1>>>(nb);
    k_scan3<<<nb, SCAN_B>>>(n);
    k_fill <<<(e + 255) / 256, 256>>>(src, dst, e);
    k_wfrag<<<4, 256>>>(W1, W2, W3, W4);

    int ntiles = (n + 127) / 128;
    int ggrid  = ntiles < 296 ? ntiles : 296;
    int agg_grid = (n * 32 + 255) / 256;

    // layer 1: x -> h
    k_gemm_mma<<<ggrid, 256, GM_SMEM>>>(x, wf + 0 * 16384, t, n, ntiles);
    k_agg     <<<agg_grid, 256>>>(t, b1, h, n);
    // layer 2: h -> h2
    k_gemm_mma<<<ggrid, 256, GM_SMEM>>>(h, wf + 1 * 16384, t, n, ntiles);
    k_agg     <<<agg_grid, 256>>>(t, b2, h2, n);
    // layer 3: h2 -> h
    k_gemm_mma<<<ggrid, 256, GM_SMEM>>>(h2, wf + 2 * 16384, t, n, ntiles);
    k_agg     <<<agg_grid, 256>>>(t, b3, h, n);
    // layer 4: h -> h2
    k_gemm_mma<<<ggrid, 256, GM_SMEM>>>(h, wf + 3 * 16384, t, n, ntiles);
    k_agg     <<<agg_grid, 256>>>(t, b4, h2, n);

    k_colsum<<<240, D>>>(h2, n);
    k_mlp<<<1, D>>>(Wl1, bl1, Wl2, bl2, Wo, bo, out, n);
}

// round 6
// speedup vs baseline: 1.2980x; 1.0739x over previous
#include <cuda_runtime.h>
#include <cuda_bf16.h>
#include <cstdint>

// Problem constants: N=100000 nodes, E=1.6M edges, D=128.
#define NMAX 100000
#define EMAX 1600000
#define D 128
#define SCAN_B 1024

// ================= scratch (static device globals) ================================
__device__ int   g_deg_out[NMAX];
__device__ int   g_deg_in [NMAX];
__device__ float g_inv_out[NMAX];
__device__ float g_inv_in [NMAX];
__device__ int   g_row_off[NMAX + 1];
__device__ int   g_cursor [NMAX];
__device__ int   g_csr    [EMAX];
__device__ int   g_bsum   [256];
__device__ int   g_boff   [257];
__device__ float g_h      [(size_t)NMAX * D];
__device__ float g_h2     [(size_t)NMAX * D];
__device__ __nv_bfloat16 g_t[(size_t)NMAX * D];   // bf16 gather tensor
__device__ float g_colsum [D];
// W fragments per layer: [kit(16)][nt2(8)][lane(32)] x float4 = 16384 floats / layer
__device__ float g_wfrag  [4 * 16384];

// tf32 round-to-nearest; cvt.rna.tf32.f32 requires b32 destination
__device__ __forceinline__ float to_tf32(float x) {
    uint32_t r;
    asm("cvt.rna.tf32.f32 %0, %1;" : "=r"(r) : "f"(x));
    return __uint_as_float(r);
}

// m16n8k8 tf32 MMA, fp32 accumulate in place
__device__ __forceinline__ void mma_tf32(float* c, uint32_t a0, uint32_t a1,
                                         uint32_t a2, uint32_t a3,
                                         uint32_t b0, uint32_t b1) {
    asm volatile(
        "mma.sync.aligned.m16n8k8.row.col.f32.tf32.tf32.f32 "
        "{%0,%1,%2,%3}, {%4,%5,%6,%7}, {%8,%9}, {%0,%1,%2,%3};"
        : "+f"(c[0]), "+f"(c[1]), "+f"(c[2]), "+f"(c[3])
        : "r"(a0), "r"(a1), "r"(a2), "r"(a3), "r"(b0), "r"(b1));
}

// ================= setup kernels ==================================================
__global__ void k_zero(int n) {
    int i = blockIdx.x * blockDim.x + threadIdx.x;
    if (i < n) { g_deg_out[i] = 0; g_deg_in[i] = 0; g_cursor[i] = 0; }
    if (i < D) g_colsum[i] = 0.0f;
}

__global__ void k_deg(const int* __restrict__ src, const int* __restrict__ dst, int e) {
    int i = blockIdx.x * blockDim.x + threadIdx.x;
    if (i < e) {
        atomicAdd(&g_deg_out[src[i]], 1);
        atomicAdd(&g_deg_in [dst[i]], 1);
    }
}

__global__ void k_inv(int n) {
    int i = blockIdx.x * blockDim.x + threadIdx.x;
    if (i < n) {
        g_inv_out[i] = rsqrtf((float)max(g_deg_out[i], 1));
        g_inv_in [i] = rsqrtf((float)max(g_deg_in [i], 1));
    }
}

__global__ void k_scan1(int n) {
    __shared__ int s[SCAN_B];
    int t = threadIdx.x;
    int i = blockIdx.x * SCAN_B + t;
    int v = (i < n) ? g_deg_in[i] : 0;
    s[t] = v;
    __syncthreads();
    for (int off = 1; off < SCAN_B; off <<= 1) {
        int x = 0;
        if (t >= off) x = s[t - off];
        __syncthreads();
        s[t] += x;
        __syncthreads();
    }
    if (i < n) g_row_off[i + 1] = s[t];
    if (t == SCAN_B - 1) g_bsum[blockIdx.x] = s[t];
}

__global__ void k_scan2(int nb) {
    if (threadIdx.x == 0 && blockIdx.x == 0) {
        int acc = 0;
        for (int i = 0; i < nb; i++) { g_boff[i] = acc; acc += g_bsum[i]; }
        g_boff[nb] = acc;
    }
}

__global__ void k_scan3(int n) {
    int t = threadIdx.x;
    int i = blockIdx.x * SCAN_B + t;
    if (i < n) g_row_off[i + 1] += g_boff[blockIdx.x];
    if (i == 0) g_row_off[0] = 0;
}

__global__ void k_fill(const int* __restrict__ src, const int* __restrict__ dst, int e) {
    int i = blockIdx.x * blockDim.x + threadIdx.x;
    if (i < e) {
        int d = dst[i];
        int p = g_row_off[d] + atomicAdd(&g_cursor[d], 1);
        g_csr[p] = src[i];
    }
}

// Pack W (128x128 row-major, [k][n]) into mma fragment-major layout per layer:
// float4 at [(kit*8 + nt2)*32 + lane] = { b0(nt=2*nt2), b1(nt), b0(nt+1), b1(nt+1) }
// where b0 = W[kit*8 + lane%4][n0 + lane/4], b1 = W[kit*8+4+lane%4][n0 + lane/4].
__global__ void k_wfrag(const float* __restrict__ W1, const float* __restrict__ W2,
                        const float* __restrict__ W3, const float* __restrict__ W4) {
    const float* W = (blockIdx.x == 0) ? W1 : (blockIdx.x == 1) ? W2
                   : (blockIdx.x == 2) ? W3 : W4;
    float4* out = (float4*)&g_wfrag[(size_t)blockIdx.x * 16384];
    for (int i = threadIdx.x; i < 4096; i += blockDim.x) {
        int lane = i & 31;
        int nt2  = (i >> 5) & 7;
        int kit  = i >> 8;
        int kk = kit * 8 + (lane & 3);
        int c0 = nt2 * 16 + (lane >> 2);
        float4 v;
        v.x = to_tf32(W[kk * D + c0]);
        v.y = to_tf32(W[(kk + 4) * D + c0]);
        v.z = to_tf32(W[kk * D + c0 + 8]);
        v.w = to_tf32(W[(kk + 4) * D + c0 + 8]);
        out[i] = v;
    }
}

// ================= tensor-core GEMM: t = (diag(inv_out) * hin) @ W, bf16 out ======
// mma.sync m16n8k8 tf32. CTA tile 128x128, 8 warps, warp tile 32x64.
// Shared: W-frags 64KB (loaded once per persistent CTA) + A chunk 128x32 (pad 36).
#define GM_SW_F4 4096                 // float4 count of W-frag buffer
#define GM_SA_OFF (GM_SW_F4 * 16)     // byte offset of A buffer
#define GM_SMEM (GM_SA_OFF + 128 * 36 * 4)   // 65536 + 18432 = 83968 B

__global__ void __launch_bounds__(256, 2)
k_gemm_mma(const float* __restrict__ hin, const float* __restrict__ wfrag,
           __nv_bfloat16* __restrict__ tout, int n, int ntiles) {
    extern __shared__ char smem[];
    float4* sW = (float4*)smem;
    float*  sA = (float*)(smem + GM_SA_OFF);

    int tid = threadIdx.x;
    int w = tid >> 5, lane = tid & 31;
    int qr = lane >> 2;        // 0..7
    int qc = lane & 3;         // 0..3
    int mrow = (w & 3) * 32;   // warp row base within tile
    int nc2_0 = (w >> 2) * 4;  // warp nt2 base (cols (w>>2)*64)
    int ncol = (w >> 2) * 64;

    // stage W fragments once
    const float4* wf4 = (const float4*)wfrag;
    for (int i = tid; i < GM_SW_F4; i += 256) sW[i] = wf4[i];
    // (first __syncthreads inside the kc loop covers this)

    for (int tile = blockIdx.x; tile < ntiles; tile += gridDim.x) {
        int row0 = tile * 128;
        float acc[2][8][4];
        #pragma unroll
        for (int s = 0; s < 2; s++)
            #pragma unroll
            for (int nt = 0; nt < 8; nt++)
                #pragma unroll
                for (int j = 0; j < 4; j++) acc[s][nt][j] = 0.0f;

        #pragma unroll
        for (int kc = 0; kc < 4; kc++) {
            __syncthreads();   // prior chunk's reads done (also fences sW load)
            // stage A chunk: 128 rows x 32 cols, scaled + tf32-rounded
            for (int i = tid; i < 1024; i += 256) {
                int r  = i >> 3;
                int c4 = (i & 7) * 4;
                int gr = row0 + r;
                float4 v = make_float4(0.f, 0.f, 0.f, 0.f);
                if (gr < n) {
                    v = *(const float4*)&hin[(size_t)gr * D + kc * 32 + c4];
                    float s = g_inv_out[gr];
                    v.x = to_tf32(v.x * s); v.y = to_tf32(v.y * s);
                    v.z = to_tf32(v.z * s); v.w = to_tf32(v.w * s);
                }
                *(float4*)&sA[r * 36 + c4] = v;
            }
            __syncthreads();

            #pragma unroll
            for (int kit = 0; kit < 4; kit++) {
                int kitg = kc * 4 + kit;
                // A fragments: j = slab*2 + half; row = mrow + slab*16 + half*8 + qr
                uint32_t a[4][2];
                #pragma unroll
                for (int j = 0; j < 4; j++) {
                    int r = mrow + ((j >> 1) << 4) + ((j & 1) << 3) + qr;
                    a[j][0] = __float_as_uint(sA[r * 36 + kit * 8 + qc]);
                    a[j][1] = __float_as_uint(sA[r * 36 + kit * 8 + 4 + qc]);
                }
                #pragma unroll
                for (int i = 0; i < 4; i++) {
                    float4 bb = sW[(kitg * 8 + nc2_0 + i) * 32 + lane];
                    uint32_t b0a = __float_as_uint(bb.x), b1a = __float_as_uint(bb.y);
                    uint32_t b0b = __float_as_uint(bb.z), b1b = __float_as_uint(bb.w);
                    #pragma unroll
                    for (int s = 0; s < 2; s++) {
                        mma_tf32(acc[s][2 * i],
                                 a[s * 2][0], a[s * 2 + 1][0],
                                 a[s * 2][1], a[s * 2 + 1][1], b0a, b1a);
                        mma_tf32(acc[s][2 * i + 1],
                                 a[s * 2][0], a[s * 2 + 1][0],
                                 a[s * 2][1], a[s * 2 + 1][1], b0b, b1b);
                    }
                }
            }
        }

        // epilogue: pack fp32 pairs -> bf16x2; c0/c1 -> (row, col..col+1), c2/c3 -> row+8
        #pragma unroll
        for (int s = 0; s < 2; s++) {
            int r0g = row0 + mrow + s * 16 + qr;
            int r1g = r0g + 8;
            #pragma unroll
            for (int nt = 0; nt < 8; nt++) {
                int col = ncol + nt * 8 + qc * 2;
                if (r0g < n) {
                    __nv_bfloat162 o = __floats2bfloat162_rn(acc[s][nt][0], acc[s][nt][1]);
                    *(__nv_bfloat162*)&tout[(size_t)r0g * D + col] = o;
                }
                if (r1g < n) {
                    __nv_bfloat162 o = __floats2bfloat162_rn(acc[s][nt][2], acc[s][nt][3]);
                    *(__nv_bfloat162*)&tout[(size_t)r1g * D + col] = o;
                }
            }
        }
    }
}

// ================= aggregation: bf16 gathers, fp32 accumulate =====================
// one warp per node; lane owns 4 contiguous cols (one uint2 = 4 bf16 = 8B).
// 32 lanes x 8B = 256B per edge row, fully coalesced (2 x 128B lines).
__global__ void __launch_bounds__(256)
k_agg(const __nv_bfloat16* __restrict__ tin, const float* __restrict__ b,
      float* __restrict__ hout, int n) {
    int warp = (blockIdx.x * blockDim.x + threadIdx.x) >> 5;
    int lane = threadIdx.x & 31;
    if (warp >= n) return;

    int s = g_row_off[warp];
    int e = g_row_off[warp + 1];
    int coff = lane * 4;

    float ax = 0.f, ay = 0.f, az = 0.f, aw = 0.f;
    int i = s;
    for (; i + 4 <= e; i += 4) {
        int s0 = g_csr[i], s1 = g_csr[i + 1], s2 = g_csr[i + 2], s3 = g_csr[i + 3];
        uint2 v0 = *(const uint2*)&tin[(size_t)s0 * D + coff];
        uint2 v1 = *(const uint2*)&tin[(size_t)s1 * D + coff];
        uint2 v2 = *(const uint2*)&tin[(size_t)s2 * D + coff];
        uint2 v3 = *(const uint2*)&tin[(size_t)s3 * D + coff];
        float2 a0 = __bfloat1622float2(*(__nv_bfloat162*)&v0.x);
        float2 b0 = __bfloat1622float2(*(__nv_bfloat162*)&v0.y);
        float2 a1 = __bfloat1622float2(*(__nv_bfloat162*)&v1.x);
        float2 b1 = __bfloat1622float2(*(__nv_bfloat162*)&v1.y);
        float2 a2 = __bfloat1622float2(*(__nv_bfloat162*)&v2.x);
        float2 b2 = __bfloat1622float2(*(__nv_bfloat162*)&v2.y);
        float2 a3 = __bfloat1622float2(*(__nv_bfloat162*)&v3.x);
        float2 b3 = __bfloat1622float2(*(__nv_bfloat162*)&v3.y);
        ax += (a0.x + a1.x) + (a2.x + a3.x);
        ay += (a0.y + a1.y) + (a2.y + a3.y);
        az += (b0.x + b1.x) + (b2.x + b3.x);
        aw += (b0.y + b1.y) + (b2.y + b3.y);
    }
    for (; i < e; i++) {
        int s0 = g_csr[i];
        uint2 v0 = *(const uint2*)&tin[(size_t)s0 * D + coff];
        float2 a0 = __bfloat1622float2(*(__nv_bfloat162*)&v0.x);
        float2 b0 = __bfloat1622float2(*(__nv_bfloat162*)&v0.y);
        ax += a0.x; ay += a0.y; az += b0.x; aw += b0.y;
    }

    float inv = g_inv_in[warp];
    float4 bb = *(const float4*)&b[coff];
    float4 o;
    o.x = fmaxf(fmaf(ax, inv, bb.x), 0.f);
    o.y = fmaxf(fmaf(ay, inv, bb.y), 0.f);
    o.z = fmaxf(fmaf(az, inv, bb.z), 0.f);
    o.w = fmaxf(fmaf(aw, inv, bb.w), 0.f);
    *(float4*)&hout[(size_t)warp * D + coff] = o;
}

// ================= epilogue =======================================================
__global__ void k_colsum(const float* __restrict__ h, int n) {
    int c = threadIdx.x;
    int rows_per = (n + gridDim.x - 1) / gridDim.x;
    int r0 = blockIdx.x * rows_per;
    int r1 = min(n, r0 + rows_per);
    float acc = 0.f;
    for (int r = r0; r < r1; r++) acc += h[(size_t)r * D + c];
    atomicAdd(&g_colsum[c], acc);
}

__global__ void k_mlp(const float* __restrict__ Wl1, const float* __restrict__ bl1,
                      const float* __restrict__ Wl2, const float* __restrict__ bl2,
                      const float* __restrict__ Wo,  const float* __restrict__ bo,
                      float* __restrict__ out, int n) {
    __shared__ float s0[D], s1[D], s2[D];
    int t = threadIdx.x;
    s0[t] = g_colsum[t] * (1.0f / (float)n);
    __syncthreads();

    float a = bl1[t];
    for (int k = 0; k < D; k++) a = fmaf(s0[k], Wl1[k * D + t], a);
    s1[t] = fmaxf(a, 0.f);
    __syncthreads();

    float a2 = bl2[t];
    for (int k = 0; k < D; k++) a2 = fmaf(s1[k], Wl2[k * D + t], a2);
    s2[t] = fmaxf(a2, 0.f) * Wo[t];
    __syncthreads();

    for (int off = 64; off > 0; off >>= 1) {
        if (t < off) s2[t] += s2[t + off];
        __syncthreads();
    }
    if (t == 0) out[0] = s2[0] + bo[0];
}

// ================= launch =========================================================
extern "C" void kernel_launch(void* const* d_in, const int* in_sizes, int n_in,
                              void* d_out, int out_size) {
    const float* x   = (const float*)d_in[0];
    const int*   src = (const int*)  d_in[1];
    const int*   dst = (const int*)  d_in[2];
    const float* W1  = (const float*)d_in[3];
    const float* b1  = (const float*)d_in[4];
    const float* W2  = (const float*)d_in[5];
    const float* b2  = (const float*)d_in[6];
    const float* W3  = (const float*)d_in[7];
    const float* b3  = (const float*)d_in[8];
    const float* W4  = (const float*)d_in[9];
    const float* b4  = (const float*)d_in[10];
    const float* Wl1 = (const float*)d_in[11];
    const float* bl1 = (const float*)d_in[12];
    const float* Wl2 = (const float*)d_in[13];
    const float* bl2 = (const float*)d_in[14];
    const float* Wo  = (const float*)d_in[15];
    const float* bo  = (const float*)d_in[16];
    float* out = (float*)d_out;

    int n = in_sizes[0] / D;
    int e = in_sizes[1];

    cudaFuncSetAttribute(k_gemm_mma, cudaFuncAttributeMaxDynamicSharedMemorySize,
                         GM_SMEM);

    float *h, *h2, *wf;
    __nv_bfloat16* t;
    cudaGetSymbolAddress((void**)&h,  g_h);
    cudaGetSymbolAddress((void**)&h2, g_h2);
    cudaGetSymbolAddress((void**)&t,  g_t);
    cudaGetSymbolAddress((void**)&wf, g_wfrag);

    int nb = (n + SCAN_B - 1) / SCAN_B;

    k_zero <<<(n + 255) / 256, 256>>>(n);
    k_deg  <<<(e + 255) / 256, 256>>>(src, dst, e);
    k_inv  <<<(n + 255) / 256, 256>>>(n);
    k_scan1<<<nb, SCAN_B>>>(n);
    k_scan2<<<1, 1>>>(nb);
    k_scan3<<<nb, SCAN_B>>>(n);
    k_fill <<<(e + 255) / 256, 256>>>(src, dst, e);
    k_wfrag<<<4, 256>>>(W1, W2, W3, W4);

    int ntiles = (n + 127) / 128;
    int ggrid  = ntiles < 296 ? ntiles : 296;
    int agg_grid = (n * 32 + 255) / 256;

    // layer 1: x -> h
    k_gemm_mma<<<ggrid, 256, GM_SMEM>>>(x, wf + 0 * 16384, t, n, ntiles);
    k_agg     <<<agg_grid, 256>>>(t, b1, h, n);
    // layer 2: h -> h2
    k_gemm_mma<<<ggrid, 256, GM_SMEM>>>(h, wf + 1 * 16384, t, n, ntiles);
    k_agg     <<<agg_grid, 256>>>(t, b2, h2, n);
    // layer 3: h2 -> h
    k_gemm_mma<<<ggrid, 256, GM_SMEM>>>(h2, wf + 2 * 16384, t, n, ntiles);
    k_agg     <<<agg_grid, 256>>>(t, b3, h, n);
    // layer 4: h -> h2
    k_gemm_mma<<<ggrid, 256, GM_SMEM>>>(h, wf + 3 * 16384, t, n, ntiles);
    k_agg     <<<agg_grid, 256>>>(t, b4, h2, n);

    k_colsum<<<240, D>>>(h2, n);
    k_mlp<<<1, D>>>(Wl1, bl1, Wl2, bl2, Wo, bo, out, n);
}

// round 7
// speedup vs baseline: 1.3481x; 1.0386x over previous
#include <cuda_runtime.h>
#include <cuda_bf16.h>
#include <cstdint>

// Problem constants: N=100000 nodes, E=1.6M edges, D=128.
#define NMAX 100000
#define EMAX 1600000
#define D 128
#define SCAN_B 1024

// ================= scratch (static device globals) ================================
__device__ int   g_deg_out[NMAX];
__device__ int   g_deg_in [NMAX];
__device__ float g_inv_out[NMAX];
__device__ float g_inv_in [NMAX];
__device__ int   g_row_off[NMAX + 1];
__device__ int   g_cursor [NMAX];
__device__ int   g_csr    [EMAX];
__device__ int   g_bsum   [256];
__device__ int   g_bflag  [256];
__device__ float g_h      [(size_t)NMAX * D];
__device__ float g_h2     [(size_t)NMAX * D];
__device__ __nv_bfloat16 g_t[(size_t)NMAX * D];   // bf16 gather tensor
__device__ float g_colsum [D];
// W fragments per layer: [kit(16)][nt2(8)][lane(32)] x float4 = 16384 floats / layer
__device__ float g_wfrag  [4 * 16384];

// tf32 round-to-nearest; cvt.rna.tf32.f32 requires b32 destination
__device__ __forceinline__ float to_tf32(float x) {
    uint32_t r;
    asm("cvt.rna.tf32.f32 %0, %1;" : "=r"(r) : "f"(x));
    return __uint_as_float(r);
}

// m16n8k8 tf32 MMA, fp32 accumulate in place
__device__ __forceinline__ void mma_tf32(float* c, uint32_t a0, uint32_t a1,
                                         uint32_t a2, uint32_t a3,
                                         uint32_t b0, uint32_t b1) {
    asm volatile(
        "mma.sync.aligned.m16n8k8.row.col.f32.tf32.tf32.f32 "
        "{%0,%1,%2,%3}, {%4,%5,%6,%7}, {%8,%9}, {%0,%1,%2,%3};"
        : "+f"(c[0]), "+f"(c[1]), "+f"(c[2]), "+f"(c[3])
        : "r"(a0), "r"(a1), "r"(a2), "r"(a3), "r"(b0), "r"(b1));
}

// ================= setup kernels ==================================================
__global__ void k_zero(int n) {
    int i = blockIdx.x * blockDim.x + threadIdx.x;
    if (i < n) { g_deg_out[i] = 0; g_deg_in[i] = 0; g_cursor[i] = 0; }
    if (i < D) g_colsum[i] = 0.0f;
    if (i < 256) g_bflag[i] = 0;
}

__global__ void k_deg(const int* __restrict__ src, const int* __restrict__ dst, int e) {
    int i = blockIdx.x * blockDim.x + threadIdx.x;
    if (i < e) {
        atomicAdd(&g_deg_out[src[i]], 1);
        atomicAdd(&g_deg_in [dst[i]], 1);
    }
}

// Fused: inv_sqrt degrees + full prefix scan of deg_in (decoupled aggregates).
// All 98 blocks are co-resident (<= #SMs), so flag-spin cannot deadlock:
// every block publishes its aggregate BEFORE spinning on predecessors.
__global__ void k_scanf(int n) {
    __shared__ int ssc[SCAN_B];
    __shared__ int swr[32];
    int t = threadIdx.x;
    int i = blockIdx.x * SCAN_B + t;

    if (i < n) {
        g_inv_out[i] = rsqrtf((float)max(g_deg_out[i], 1));
        g_inv_in [i] = rsqrtf((float)max(g_deg_in [i], 1));
    }

    int v = (i < n) ? g_deg_in[i] : 0;
    ssc[t] = v;
    __syncthreads();
    for (int off = 1; off < SCAN_B; off <<= 1) {
        int x = 0;
        if (t >= off) x = ssc[t - off];
        __syncthreads();
        ssc[t] += x;
        __syncthreads();
    }

    // publish block aggregate
    if (t == SCAN_B - 1) {
        g_bsum[blockIdx.x] = ssc[t];
        __threadfence();
        atomicExch(&g_bflag[blockIdx.x], 1);
    }

    // sum predecessors' aggregates (parallel spin, one flag per thread)
    int part = 0;
    if (t < blockIdx.x) {
        while (((volatile int*)g_bflag)[t] == 0) {}
        part = ((volatile int*)g_bsum)[t];
    }
    #pragma unroll
    for (int off = 16; off > 0; off >>= 1)
        part += __shfl_down_sync(0xffffffffu, part, off);
    if ((t & 31) == 0) swr[t >> 5] = part;
    __syncthreads();
    if (t < 32) {
        int p = swr[t];
        #pragma unroll
        for (int off = 16; off > 0; off >>= 1)
            p += __shfl_down_sync(0xffffffffu, p, off);
        if (t == 0) swr[0] = p;
    }
    __syncthreads();
    int offset = swr[0];

    if (i < n) g_row_off[i + 1] = ssc[t] + offset;
    if (i == 0) g_row_off[0] = 0;
}

// Fused: CSR fill + weight-fragment packing (blocks 0..3 also pack one W each).
// float4 at [(kit*8 + nt2)*32 + lane] = { b0(nt=2*nt2), b1(nt), b0(nt+1), b1(nt+1) }
__global__ void k_fillw(const int* __restrict__ src, const int* __restrict__ dst, int e,
                        const float* __restrict__ W1, const float* __restrict__ W2,
                        const float* __restrict__ W3, const float* __restrict__ W4) {
    int i = blockIdx.x * blockDim.x + threadIdx.x;
    if (i < e) {
        int d = dst[i];
        int p = g_row_off[d] + atomicAdd(&g_cursor[d], 1);
        g_csr[p] = src[i];
    }
    if (blockIdx.x < 4) {
        const float* W = (blockIdx.x == 0) ? W1 : (blockIdx.x == 1) ? W2
                       : (blockIdx.x == 2) ? W3 : W4;
        float4* out = (float4*)&g_wfrag[(size_t)blockIdx.x * 16384];
        for (int j = threadIdx.x; j < 4096; j += blockDim.x) {
            int lane = j & 31;
            int nt2  = (j >> 5) & 7;
            int kit  = j >> 8;
            int kk = kit * 8 + (lane & 3);
            int c0 = nt2 * 16 + (lane >> 2);
            float4 v;
            v.x = to_tf32(W[kk * D + c0]);
            v.y = to_tf32(W[(kk + 4) * D + c0]);
            v.z = to_tf32(W[kk * D + c0 + 8]);
            v.w = to_tf32(W[(kk + 4) * D + c0 + 8]);
            out[j] = v;
        }
    }
}

// ================= tensor-core GEMM: t = (diag(inv_out) * hin) @ W, bf16 out ======
// mma.sync m16n8k8 tf32. CTA tile 128x128, 8 warps, warp tile 32x64.
#define GM_SW_F4 4096                 // float4 count of W-frag buffer
#define GM_SA_OFF (GM_SW_F4 * 16)     // byte offset of A buffer
#define GM_SMEM (GM_SA_OFF + 128 * 36 * 4)   // 65536 + 18432 = 83968 B

__global__ void __launch_bounds__(256, 2)
k_gemm_mma(const float* __restrict__ hin, const float* __restrict__ wfrag,
           __nv_bfloat16* __restrict__ tout, int n, int ntiles) {
    extern __shared__ char smem[];
    float4* sW = (float4*)smem;
    float*  sA = (float*)(smem + GM_SA_OFF);

    int tid = threadIdx.x;
    int w = tid >> 5, lane = tid & 31;
    int qr = lane >> 2;        // 0..7
    int qc = lane & 3;         // 0..3
    int mrow = (w & 3) * 32;   // warp row base within tile
    int nc2_0 = (w >> 2) * 4;  // warp nt2 base (cols (w>>2)*64)
    int ncol = (w >> 2) * 64;

    // stage W fragments once
    const float4* wf4 = (const float4*)wfrag;
    for (int i = tid; i < GM_SW_F4; i += 256) sW[i] = wf4[i];
    // (first __syncthreads inside the kc loop covers this)

    for (int tile = blockIdx.x; tile < ntiles; tile += gridDim.x) {
        int row0 = tile * 128;
        float acc[2][8][4];
        #pragma unroll
        for (int s = 0; s < 2; s++)
            #pragma unroll
            for (int nt = 0; nt < 8; nt++)
                #pragma unroll
                for (int j = 0; j < 4; j++) acc[s][nt][j] = 0.0f;

        #pragma unroll
        for (int kc = 0; kc < 4; kc++) {
            __syncthreads();   // prior chunk's reads done (also fences sW load)
            // stage A chunk: 128 rows x 32 cols, scaled + tf32-rounded
            for (int i = tid; i < 1024; i += 256) {
                int r  = i >> 3;
                int c4 = (i & 7) * 4;
                int gr = row0 + r;
                float4 v = make_float4(0.f, 0.f, 0.f, 0.f);
                if (gr < n) {
                    v = *(const float4*)&hin[(size_t)gr * D + kc * 32 + c4];
                    float s = g_inv_out[gr];
                    v.x = to_tf32(v.x * s); v.y = to_tf32(v.y * s);
                    v.z = to_tf32(v.z * s); v.w = to_tf32(v.w * s);
                }
                *(float4*)&sA[r * 36 + c4] = v;
            }
            __syncthreads();

            #pragma unroll
            for (int kit = 0; kit < 4; kit++) {
                int kitg = kc * 4 + kit;
                uint32_t a[4][2];
                #pragma unroll
                for (int j = 0; j < 4; j++) {
                    int r = mrow + ((j >> 1) << 4) + ((j & 1) << 3) + qr;
                    a[j][0] = __float_as_uint(sA[r * 36 + kit * 8 + qc]);
                    a[j][1] = __float_as_uint(sA[r * 36 + kit * 8 + 4 + qc]);
                }
                #pragma unroll
                for (int i = 0; i < 4; i++) {
                    float4 bb = sW[(kitg * 8 + nc2_0 + i) * 32 + lane];
                    uint32_t b0a = __float_as_uint(bb.x), b1a = __float_as_uint(bb.y);
                    uint32_t b0b = __float_as_uint(bb.z), b1b = __float_as_uint(bb.w);
                    #pragma unroll
                    for (int s = 0; s < 2; s++) {
                        mma_tf32(acc[s][2 * i],
                                 a[s * 2][0], a[s * 2 + 1][0],
                                 a[s * 2][1], a[s * 2 + 1][1], b0a, b1a);
                        mma_tf32(acc[s][2 * i + 1],
                                 a[s * 2][0], a[s * 2 + 1][0],
                                 a[s * 2][1], a[s * 2 + 1][1], b0b, b1b);
                    }
                }
            }
        }

        // epilogue: pack fp32 pairs -> bf16x2
        #pragma unroll
        for (int s = 0; s < 2; s++) {
            int r0g = row0 + mrow + s * 16 + qr;
            int r1g = r0g + 8;
            #pragma unroll
            for (int nt = 0; nt < 8; nt++) {
                int col = ncol + nt * 8 + qc * 2;
                if (r0g < n) {
                    __nv_bfloat162 o = __floats2bfloat162_rn(acc[s][nt][0], acc[s][nt][1]);
                    *(__nv_bfloat162*)&tout[(size_t)r0g * D + col] = o;
                }
                if (r1g < n) {
                    __nv_bfloat162 o = __floats2bfloat162_rn(acc[s][nt][2], acc[s][nt][3]);
                    *(__nv_bfloat162*)&tout[(size_t)r1g * D + col] = o;
                }
            }
        }
    }
}

// ================= aggregation v2: warp-wide index prefetch + 8-deep gathers ======
// One warp per node; lane owns 4 bf16 cols (8B load). 32 CSR indices fetched with a
// single coalesced LDG, broadcast via shfl; gathers batched 8-deep for MLP >= 8.
__device__ __forceinline__ void agg_accum(const __nv_bfloat16* __restrict__ tin,
                                          int idx, int coff,
                                          float& ax, float& ay, float& az, float& aw) {
    uint2 v = *(const uint2*)&tin[(size_t)idx * D + coff];
    float2 a = __bfloat1622float2(*(__nv_bfloat162*)&v.x);
    float2 b = __bfloat1622float2(*(__nv_bfloat162*)&v.y);
    ax += a.x; ay += a.y; az += b.x; aw += b.y;
}

__global__ void __launch_bounds__(256)
k_agg(const __nv_bfloat16* __restrict__ tin, const float* __restrict__ b,
      float* __restrict__ hout, int n, int last) {
    __shared__ float sCol[D];
    int tid = threadIdx.x;
    if (last) {
        if (tid < D) sCol[tid] = 0.0f;
        __syncthreads();
    }

    int warp = (blockIdx.x * blockDim.x + tid) >> 5;
    int lane = tid & 31;
    int coff = lane * 4;

    if (warp < n) {
        int s = g_row_off[warp];
        int e = g_row_off[warp + 1];

        float ax = 0.f, ay = 0.f, az = 0.f, aw = 0.f;

        for (int base = s; base < e; base += 32) {
            int m = e - base;
            if (m > 32) m = 32;
            int idx = 0;
            if (lane < m) idx = g_csr[base + lane];   // one coalesced LDG

            int j = 0;
            for (; j + 8 <= m; j += 8) {
                int i0 = __shfl_sync(0xffffffffu, idx, j + 0);
                int i1 = __shfl_sync(0xffffffffu, idx, j + 1);
                int i2 = __shfl_sync(0xffffffffu, idx, j + 2);
                int i3 = __shfl_sync(0xffffffffu, idx, j + 3);
                int i4 = __shfl_sync(0xffffffffu, idx, j + 4);
                int i5 = __shfl_sync(0xffffffffu, idx, j + 5);
                int i6 = __shfl_sync(0xffffffffu, idx, j + 6);
                int i7 = __shfl_sync(0xffffffffu, idx, j + 7);
                // issue all 8 gathers before any conversion/accumulation
                uint2 v0 = *(const uint2*)&tin[(size_t)i0 * D + coff];
                uint2 v1 = *(const uint2*)&tin[(size_t)i1 * D + coff];
                uint2 v2 = *(const uint2*)&tin[(size_t)i2 * D + coff];
                uint2 v3 = *(const uint2*)&tin[(size_t)i3 * D + coff];
                uint2 v4 = *(const uint2*)&tin[(size_t)i4 * D + coff];
                uint2 v5 = *(const uint2*)&tin[(size_t)i5 * D + coff];
                uint2 v6 = *(const uint2*)&tin[(size_t)i6 * D + coff];
                uint2 v7 = *(const uint2*)&tin[(size_t)i7 * D + coff];
                float2 p0 = __bfloat1622float2(*(__nv_bfloat162*)&v0.x);
                float2 q0 = __bfloat1622float2(*(__nv_bfloat162*)&v0.y);
                float2 p1 = __bfloat1622float2(*(__nv_bfloat162*)&v1.x);
                float2 q1 = __bfloat1622float2(*(__nv_bfloat162*)&v1.y);
                float2 p2 = __bfloat1622float2(*(__nv_bfloat162*)&v2.x);
                float2 q2 = __bfloat1622float2(*(__nv_bfloat162*)&v2.y);
                float2 p3 = __bfloat1622float2(*(__nv_bfloat162*)&v3.x);
                float2 q3 = __bfloat1622float2(*(__nv_bfloat162*)&v3.y);
                float2 p4 = __bfloat1622float2(*(__nv_bfloat162*)&v4.x);
                float2 q4 = __bfloat1622float2(*(__nv_bfloat162*)&v4.y);
                float2 p5 = __bfloat1622float2(*(__nv_bfloat162*)&v5.x);
                float2 q5 = __bfloat1622float2(*(__nv_bfloat162*)&v5.y);
                float2 p6 = __bfloat1622float2(*(__nv_bfloat162*)&v6.x);
                float2 q6 = __bfloat1622float2(*(__nv_bfloat162*)&v6.y);
                float2 p7 = __bfloat1622float2(*(__nv_bfloat162*)&v7.x);
                float2 q7 = __bfloat1622float2(*(__nv_bfloat162*)&v7.y);
                ax += ((p0.x + p1.x) + (p2.x + p3.x)) + ((p4.x + p5.x) + (p6.x + p7.x));
                ay += ((p0.y + p1.y) + (p2.y + p3.y)) + ((p4.y + p5.y) + (p6.y + p7.y));
                az += ((q0.x + q1.x) + (q2.x + q3.x)) + ((q4.x + q5.x) + (q6.x + q7.x));
                aw += ((q0.y + q1.y) + (q2.y + q3.y)) + ((q4.y + q5.y) + (q6.y + q7.y));
            }
            for (; j < m; j++) {
                int i0 = __shfl_sync(0xffffffffu, idx, j);
                agg_accum(tin, i0, coff, ax, ay, az, aw);
            }
        }

        float inv = g_inv_in[warp];
        float4 bb = *(const float4*)&b[coff];
        float4 o;
        o.x = fmaxf(fmaf(ax, inv, bb.x), 0.f);
        o.y = fmaxf(fmaf(ay, inv, bb.y), 0.f);
        o.z = fmaxf(fmaf(az, inv, bb.z), 0.f);
        o.w = fmaxf(fmaf(aw, inv, bb.w), 0.f);
        *(float4*)&hout[(size_t)warp * D + coff] = o;

        if (last) {
            atomicAdd(&sCol[coff + 0], o.x);
            atomicAdd(&sCol[coff + 1], o.y);
            atomicAdd(&sCol[coff + 2], o.z);
            atomicAdd(&sCol[coff + 3], o.w);
        }
    }

    if (last) {
        __syncthreads();
        if (tid < D) atomicAdd(&g_colsum[tid], sCol[tid]);
    }
}

// ================= epilogue =======================================================
__global__ void k_mlp(const float* __restrict__ Wl1, const float* __restrict__ bl1,
                      const float* __restrict__ Wl2, const float* __restrict__ bl2,
                      const float* __restrict__ Wo,  const float* __restrict__ bo,
                      float* __restrict__ out, int n) {
    __shared__ float s0[D], s1[D], s2[D];
    int t = threadIdx.x;
    s0[t] = g_colsum[t] * (1.0f / (float)n);
    __syncthreads();

    float a = bl1[t];
    for (int k = 0; k < D; k++) a = fmaf(s0[k], Wl1[k * D + t], a);
    s1[t] = fmaxf(a, 0.f);
    __syncthreads();

    float a2 = bl2[t];
    for (int k = 0; k < D; k++) a2 = fmaf(s1[k], Wl2[k * D + t], a2);
    s2[t] = fmaxf(a2, 0.f) * Wo[t];
    __syncthreads();

    for (int off = 64; off > 0; off >>= 1) {
        if (t < off) s2[t] += s2[t + off];
        __syncthreads();
    }
    if (t == 0) out[0] = s2[0] + bo[0];
}

// ================= launch =========================================================
extern "C" void kernel_launch(void* const* d_in, const int* in_sizes, int n_in,
                              void* d_out, int out_size) {
    const float* x   = (const float*)d_in[0];
    const int*   src = (const int*)  d_in[1];
    const int*   dst = (const int*)  d_in[2];
    const float* W1  = (const float*)d_in[3];
    const float* b1  = (const float*)d_in[4];
    const float* W2  = (const float*)d_in[5];
    const float* b2  = (const float*)d_in[6];
    const float* W3  = (const float*)d_in[7];
    const float* b3  = (const float*)d_in[8];
    const float* W4  = (const float*)d_in[9];
    const float* b4  = (const float*)d_in[10];
    const float* Wl1 = (const float*)d_in[11];
    const float* bl1 = (const float*)d_in[12];
    const float* Wl2 = (const float*)d_in[13];
    const float* bl2 = (const float*)d_in[14];
    const float* Wo  = (const float*)d_in[15];
    const float* bo  = (const float*)d_in[16];
    float* out = (float*)d_out;

    int n = in_sizes[0] / D;
    int e = in_sizes[1];

    cudaFuncSetAttribute(k_gemm_mma, cudaFuncAttributeMaxDynamicSharedMemorySize,
                         GM_SMEM);

    float *h, *h2, *wf;
    __nv_bfloat16* t;
    cudaGetSymbolAddress((void**)&h,  g_h);
    cudaGetSymbolAddress((void**)&h2, g_h2);
    cudaGetSymbolAddress((void**)&t,  g_t);
    cudaGetSymbolAddress((void**)&wf, g_wfrag);

    int nb = (n + SCAN_B - 1) / SCAN_B;
    int ntiles = (n + 127) / 128;
    int ggrid  = ntiles < 296 ? ntiles : 296;
    int agg_grid = (n * 32 + 255) / 256;

    // launch order fixed so ncu (-s 5 -c 1) captures k_agg layer 1 at index 5
    k_zero  <<<(n + 255) / 256, 256>>>(n);                        // 0
    k_deg   <<<(e + 255) / 256, 256>>>(src, dst, e);              // 1
    k_scanf <<<nb, SCAN_B>>>(n);                                  // 2
    k_fillw <<<(e + 255) / 256, 256>>>(src, dst, e, W1, W2, W3, W4); // 3

    // layer 1: x -> h
    k_gemm_mma<<<ggrid, 256, GM_SMEM>>>(x, wf + 0 * 16384, t, n, ntiles); // 4
    k_agg     <<<agg_grid, 256>>>(t, b1, h, n, 0);                        // 5 <- ncu
    // layer 2: h -> h2
    k_gemm_mma<<<ggrid, 256, GM_SMEM>>>(h, wf + 1 * 16384, t, n, ntiles);
    k_agg     <<<agg_grid, 256>>>(t, b2, h2, n, 0);
    // layer 3: h2 -> h
    k_gemm_mma<<<ggrid, 256, GM_SMEM>>>(h2, wf + 2 * 16384, t, n, ntiles);
    k_agg     <<<agg_grid, 256>>>(t, b3, h, n, 0);
    // layer 4: h -> h2 (fused column-sum for the mean)
    k_gemm_mma<<<ggrid, 256, GM_SMEM>>>(h, wf + 3 * 16384, t, n, ntiles);
    k_agg     <<<agg_grid, 256>>>(t, b4, h2, n, 1);

    k_mlp<<<1, D>>>(Wl1, bl1, Wl2, bl2, Wo, bo, out, n);
}

// round 8
// speedup vs baseline: 1.4025x; 1.0404x over previous
#include <cuda_runtime.h>
#include <cuda_bf16.h>
#include <cstdint>

// Problem constants: N=100000 nodes, E=1.6M edges, D=128.
#define NMAX 100000
#define EMAX 1600000
#define D 128
#define SCAN_B 1024

// ================= scratch (static device globals; zero at module load) ===========
__device__ int   g_deg_out[NMAX];
__device__ int   g_deg_in [NMAX];
__device__ float g_inv_out[NMAX];
__device__ float g_inv_in [NMAX];
__device__ int   g_row_off[NMAX + 1];
__device__ int   g_cursor [NMAX];
__device__ int   g_csr    [EMAX];
__device__ int   g_bsum   [256];
__device__ int   g_bflag  [256];
__device__ float g_h      [(size_t)NMAX * D];
__device__ float g_h2     [(size_t)NMAX * D];
__device__ __nv_bfloat16 g_t[(size_t)NMAX * D];   // bf16 gather tensor
__device__ float g_colsum [D];
// W fragments per layer (bf16 m16n8k16): [kit(8)][nt2(8)][lane(32)] x uint4
__device__ uint4 g_wfrag  [4 * 2048];

__device__ __forceinline__ uint32_t pk_bf16x2(float lo, float hi) {
    __nv_bfloat162 t = __floats2bfloat162_rn(lo, hi);
    return *(uint32_t*)&t;
}

// m16n8k16 bf16 MMA, fp32 accumulate in place
__device__ __forceinline__ void mma_bf16(float* c, uint32_t a0, uint32_t a1,
                                         uint32_t a2, uint32_t a3,
                                         uint32_t b0, uint32_t b1) {
    asm volatile(
        "mma.sync.aligned.m16n8k16.row.col.f32.bf16.bf16.f32 "
        "{%0,%1,%2,%3}, {%4,%5,%6,%7}, {%8,%9}, {%0,%1,%2,%3};"
        : "+f"(c[0]), "+f"(c[1]), "+f"(c[2]), "+f"(c[3])
        : "r"(a0), "r"(a1), "r"(a2), "r"(a3), "r"(b0), "r"(b1));
}

// ================= setup kernels ==================================================
__global__ void k_deg(const int* __restrict__ src, const int* __restrict__ dst, int e) {
    int i = blockIdx.x * blockDim.x + threadIdx.x;
    if (i < e) {
        atomicAdd(&g_deg_out[src[i]], 1);
        atomicAdd(&g_deg_in [dst[i]], 1);
    }
}

// Fused: inv_sqrt degrees + full prefix scan of deg_in (decoupled aggregates).
// All 98 blocks co-resident (<= #SMs): publish aggregate BEFORE spinning.
__global__ void k_scanf(int n) {
    __shared__ int ssc[SCAN_B];
    __shared__ int swr[32];
    int t = threadIdx.x;
    int i = blockIdx.x * SCAN_B + t;

    if (i < n) {
        g_inv_out[i] = rsqrtf((float)max(g_deg_out[i], 1));
        g_inv_in [i] = rsqrtf((float)max(g_deg_in [i], 1));
    }

    int v = (i < n) ? g_deg_in[i] : 0;
    ssc[t] = v;
    __syncthreads();
    for (int off = 1; off < SCAN_B; off <<= 1) {
        int x = 0;
        if (t >= off) x = ssc[t - off];
        __syncthreads();
        ssc[t] += x;
        __syncthreads();
    }

    if (t == SCAN_B - 1) {
        g_bsum[blockIdx.x] = ssc[t];
        __threadfence();
        atomicExch(&g_bflag[blockIdx.x], 1);
    }

    int part = 0;
    if (t < blockIdx.x) {
        while (((volatile int*)g_bflag)[t] == 0) {}
        part = ((volatile int*)g_bsum)[t];
    }
    #pragma unroll
    for (int off = 16; off > 0; off >>= 1)
        part += __shfl_down_sync(0xffffffffu, part, off);
    if ((t & 31) == 0) swr[t >> 5] = part;
    __syncthreads();
    if (t < 32) {
        int p = swr[t];
        #pragma unroll
        for (int off = 16; off > 0; off >>= 1)
            p += __shfl_down_sync(0xffffffffu, p, off);
        if (t == 0) swr[0] = p;
    }
    __syncthreads();
    int offset = swr[0];

    if (i < n) g_row_off[i + 1] = ssc[t] + offset;
    if (i == 0) g_row_off[0] = 0;
}

// Fused: CSR fill + bf16 weight-fragment packing (blocks 0..3 pack one W each).
// uint4 at [(kit*8 + nt2)*32 + lane]: {b0,b1} for n-tile 2*nt2 and 2*nt2+1,
// b0 = {W[kk][c],W[kk+1][c]}, b1 = {W[kk+8][c],W[kk+9][c]},
// kk = kit*16 + (lane%4)*2, c = nt2*16 + lane/4 (and c+8 for the pair).
__global__ void k_fillw(const int* __restrict__ src, const int* __restrict__ dst, int e,
                        const float* __restrict__ W1, const float* __restrict__ W2,
                        const float* __restrict__ W3, const float* __restrict__ W4) {
    int i = blockIdx.x * blockDim.x + threadIdx.x;
    if (i < e) {
        int d = dst[i];
        int p = g_row_off[d] + atomicAdd(&g_cursor[d], 1);
        g_csr[p] = src[i];
    }
    if (blockIdx.x < 4) {
        const float* W = (blockIdx.x == 0) ? W1 : (blockIdx.x == 1) ? W2
                       : (blockIdx.x == 2) ? W3 : W4;
        uint4* out = &g_wfrag[(size_t)blockIdx.x * 2048];
        for (int j = threadIdx.x; j < 2048; j += blockDim.x) {
            int lane = j & 31;
            int nt2  = (j >> 5) & 7;
            int kit  = j >> 8;             // 0..7
            int kk = kit * 16 + (lane & 3) * 2;
            int c0 = nt2 * 16 + (lane >> 2);
            uint4 v;
            v.x = pk_bf16x2(W[kk * D + c0],        W[(kk + 1) * D + c0]);
            v.y = pk_bf16x2(W[(kk + 8) * D + c0],  W[(kk + 9) * D + c0]);
            v.z = pk_bf16x2(W[kk * D + c0 + 8],    W[(kk + 1) * D + c0 + 8]);
            v.w = pk_bf16x2(W[(kk + 8) * D + c0 + 8], W[(kk + 9) * D + c0 + 8]);
            out[j] = v;
        }
    }
}

// ================= tensor-core GEMM: t = (diag(inv_out) * hin) @ W, bf16 in/out ===
// mma.sync m16n8k16 bf16. CTA tile 128x128, 8 warps, warp tile 32x64.
// Shared: W-frags 32KB (once per persistent CTA) + A chunk 128x32 bf16 (pad 40).
#define GM_SW_U4 2048
#define GM_SA_OFF (GM_SW_U4 * 16)            // 32768 B
#define GM_SA_PAD 40                          // bf16 elements per row
#define GM_SMEM (GM_SA_OFF + 128 * GM_SA_PAD * 2)  // 32768 + 10240 = 43008 B

__global__ void __launch_bounds__(256, 2)
k_gemm_mma(const float* __restrict__ hin, const uint4* __restrict__ wfrag,
           __nv_bfloat16* __restrict__ tout, int n, int ntiles) {
    extern __shared__ char smem[];
    uint4* sW = (uint4*)smem;
    __nv_bfloat16* sA = (__nv_bfloat16*)(smem + GM_SA_OFF);

    int tid = threadIdx.x;
    int w = tid >> 5, lane = tid & 31;
    int qr = lane >> 2;        // 0..7
    int qc = lane & 3;         // 0..3
    int mrow = (w & 3) * 32;   // warp row base within tile
    int nc2_0 = (w >> 2) * 4;  // warp nt2 base (cols (w>>2)*64)
    int ncol = (w >> 2) * 64;

    // stage W fragments once
    for (int i = tid; i < GM_SW_U4; i += 256) sW[i] = wfrag[i];
    // (first __syncthreads inside the kc loop covers this)

    for (int tile = blockIdx.x; tile < ntiles; tile += gridDim.x) {
        int row0 = tile * 128;
        float acc[2][8][4];
        #pragma unroll
        for (int s = 0; s < 2; s++)
            #pragma unroll
            for (int nt = 0; nt < 8; nt++)
                #pragma unroll
                for (int j = 0; j < 4; j++) acc[s][nt][j] = 0.0f;

        #pragma unroll
        for (int kc = 0; kc < 4; kc++) {
            __syncthreads();   // prior chunk's reads done (also fences sW load)
            // stage A chunk: 128 rows x 32 k, scaled, fp32 -> bf16
            for (int i = tid; i < 1024; i += 256) {
                int r  = i >> 3;
                int c4 = (i & 7) * 4;
                int gr = row0 + r;
                uint2 u = make_uint2(0u, 0u);
                if (gr < n) {
                    float4 v = *(const float4*)&hin[(size_t)gr * D + kc * 32 + c4];
                    float s = g_inv_out[gr];
                    u.x = pk_bf16x2(v.x * s, v.y * s);
                    u.y = pk_bf16x2(v.z * s, v.w * s);
                }
                *(uint2*)&sA[r * GM_SA_PAD + c4] = u;
            }
            __syncthreads();

            #pragma unroll
            for (int kit = 0; kit < 2; kit++) {          // k16 steps in this chunk
                int kb = kit * 16 + qc * 2;              // bf16 element offset
                int kitg = kc * 2 + kit;                 // 0..7
                uint32_t a[2][4];
                #pragma unroll
                for (int s = 0; s < 2; s++) {
                    int r0 = mrow + s * 16 + qr;
                    a[s][0] = *(const uint32_t*)&sA[r0 * GM_SA_PAD + kb];
                    a[s][1] = *(const uint32_t*)&sA[(r0 + 8) * GM_SA_PAD + kb];
                    a[s][2] = *(const uint32_t*)&sA[r0 * GM_SA_PAD + kb + 8];
                    a[s][3] = *(const uint32_t*)&sA[(r0 + 8) * GM_SA_PAD + kb + 8];
                }
                #pragma unroll
                for (int i = 0; i < 4; i++) {
                    uint4 bb = sW[(kitg * 8 + nc2_0 + i) * 32 + lane];
                    #pragma unroll
                    for (int s = 0; s < 2; s++) {
                        mma_bf16(acc[s][2 * i],
                                 a[s][0], a[s][1], a[s][2], a[s][3], bb.x, bb.y);
                        mma_bf16(acc[s][2 * i + 1],
                                 a[s][0], a[s][1], a[s][2], a[s][3], bb.z, bb.w);
                    }
                }
            }
        }

        // epilogue: pack fp32 pairs -> bf16x2
        #pragma unroll
        for (int s = 0; s < 2; s++) {
            int r0g = row0 + mrow + s * 16 + qr;
            int r1g = r0g + 8;
            #pragma unroll
            for (int nt = 0; nt < 8; nt++) {
                int col = ncol + nt * 8 + qc * 2;
                if (r0g < n) {
                    __nv_bfloat162 o = __floats2bfloat162_rn(acc[s][nt][0], acc[s][nt][1]);
                    *(__nv_bfloat162*)&tout[(size_t)r0g * D + col] = o;
                }
                if (r1g < n) {
                    __nv_bfloat162 o = __floats2bfloat162_rn(acc[s][nt][2], acc[s][nt][3]);
                    *(__nv_bfloat162*)&tout[(size_t)r1g * D + col] = o;
                }
            }
        }
    }
}

// ================= aggregation v3: half-warp per node, LDG.128 gathers ============
// 16 lanes own a full 256B bf16 row (16B each). Warp = 2 nodes -> 2 edges per
// warp-instruction slot, 16 outstanding gathers. Predicated loads into
// zero-init registers (bf16 0 == +0.0f) keep batches dense.
__device__ __forceinline__ void acc8(uint4 v, float* a) {
    float2 f0 = __bfloat1622float2(*(__nv_bfloat162*)&v.x);
    float2 f1 = __bfloat1622float2(*(__nv_bfloat162*)&v.y);
    float2 f2 = __bfloat1622float2(*(__nv_bfloat162*)&v.z);
    float2 f3 = __bfloat1622float2(*(__nv_bfloat162*)&v.w);
    a[0] += f0.x; a[1] += f0.y; a[2] += f1.x; a[3] += f1.y;
    a[4] += f2.x; a[5] += f2.y; a[6] += f3.x; a[7] += f3.y;
}

__global__ void __launch_bounds__(256)
k_agg(const __nv_bfloat16* __restrict__ tin, const float* __restrict__ bias,
      float* __restrict__ hout, int n, int last) {
    __shared__ float sCol[D];
    int tid = threadIdx.x;
    if (last) {
        if (tid < D) sCol[tid] = 0.0f;
        __syncthreads();
    }

    int hw = (blockIdx.x * blockDim.x + tid) >> 4;   // half-warp = node
    int lane16 = tid & 15;
    int halfsel = tid & 16;                           // own half's lane base
    bool active = hw < n;
    int s = 0, deg = 0;
    if (active) { s = g_row_off[hw]; deg = g_row_off[hw + 1] - s; }
    int coff = lane16 * 8;                            // bf16 col offset (16B)

    float a[8];
    #pragma unroll
    for (int j = 0; j < 8; j++) a[j] = 0.0f;

    for (int base = 0; __any_sync(0xffffffffu, base < deg); base += 16) {
        int m = deg - base;
        m = (m < 0) ? 0 : (m > 16 ? 16 : m);
        int idx = 0;
        if (lane16 < m) idx = g_csr[s + base + lane16];   // coalesced per half

        #pragma unroll
        for (int jb = 0; jb < 16; jb += 8) {
            int i0 = __shfl_sync(0xffffffffu, idx, halfsel + jb + 0);
            int i1 = __shfl_sync(0xffffffffu, idx, halfsel + jb + 1);
            int i2 = __shfl_sync(0xffffffffu, idx, halfsel + jb + 2);
            int i3 = __shfl_sync(0xffffffffu, idx, halfsel + jb + 3);
            int i4 = __shfl_sync(0xffffffffu, idx, halfsel + jb + 4);
            int i5 = __shfl_sync(0xffffffffu, idx, halfsel + jb + 5);
            int i6 = __shfl_sync(0xffffffffu, idx, halfsel + jb + 6);
            int i7 = __shfl_sync(0xffffffffu, idx, halfsel + jb + 7);
            uint4 z = make_uint4(0u, 0u, 0u, 0u);
            uint4 v0 = z, v1 = z, v2 = z, v3 = z, v4 = z, v5 = z, v6 = z, v7 = z;
            if (jb + 0 < m) v0 = *(const uint4*)&tin[(size_t)i0 * D + coff];
            if (jb + 1 < m) v1 = *(const uint4*)&tin[(size_t)i1 * D + coff];
            if (jb + 2 < m) v2 = *(const uint4*)&tin[(size_t)i2 * D + coff];
            if (jb + 3 < m) v3 = *(const uint4*)&tin[(size_t)i3 * D + coff];
            if (jb + 4 < m) v4 = *(const uint4*)&tin[(size_t)i4 * D + coff];
            if (jb + 5 < m) v5 = *(const uint4*)&tin[(size_t)i5 * D + coff];
            if (jb + 6 < m) v6 = *(const uint4*)&tin[(size_t)i6 * D + coff];
            if (jb + 7 < m) v7 = *(const uint4*)&tin[(size_t)i7 * D + coff];
            acc8(v0, a); acc8(v1, a); acc8(v2, a); acc8(v3, a);
            acc8(v4, a); acc8(v5, a); acc8(v6, a); acc8(v7, a);
        }
    }

    if (active) {
        float inv = g_inv_in[hw];
        float4 b0 = *(const float4*)&bias[coff];
        float4 b1 = *(const float4*)&bias[coff + 4];
        float4 o0, o1;
        o0.x = fmaxf(fmaf(a[0], inv, b0.x), 0.f);
        o0.y = fmaxf(fmaf(a[1], inv, b0.y), 0.f);
        o0.z = fmaxf(fmaf(a[2], inv, b0.z), 0.f);
        o0.w = fmaxf(fmaf(a[3], inv, b0.w), 0.f);
        o1.x = fmaxf(fmaf(a[4], inv, b1.x), 0.f);
        o1.y = fmaxf(fmaf(a[5], inv, b1.y), 0.f);
        o1.z = fmaxf(fmaf(a[6], inv, b1.z), 0.f);
        o1.w = fmaxf(fmaf(a[7], inv, b1.w), 0.f);
        *(float4*)&hout[(size_t)hw * D + coff]     = o0;
        *(float4*)&hout[(size_t)hw * D + coff + 4] = o1;

        if (last) {
            atomicAdd(&sCol[coff + 0], o0.x); atomicAdd(&sCol[coff + 1], o0.y);
            atomicAdd(&sCol[coff + 2], o0.z); atomicAdd(&sCol[coff + 3], o0.w);
            atomicAdd(&sCol[coff + 4], o1.x); atomicAdd(&sCol[coff + 5], o1.y);
            atomicAdd(&sCol[coff + 6], o1.z); atomicAdd(&sCol[coff + 7], o1.w);
        }
    }

    if (last) {
        __syncthreads();
        if (tid < D) atomicAdd(&g_colsum[tid], sCol[tid]);
    }
}

// ================= epilogue =======================================================
__global__ void k_mlp(const float* __restrict__ Wl1, const float* __restrict__ bl1,
                      const float* __restrict__ Wl2, const float* __restrict__ bl2,
                      const float* __restrict__ Wo,  const float* __restrict__ bo,
                      float* __restrict__ out, int n) {
    __shared__ float s0[D], s1[D], s2[D];
    int t = threadIdx.x;
    s0[t] = g_colsum[t] * (1.0f / (float)n);
    __syncthreads();

    float a = bl1[t];
    for (int k = 0; k < D; k++) a = fmaf(s0[k], Wl1[k * D + t], a);
    s1[t] = fmaxf(a, 0.f);
    __syncthreads();

    float a2 = bl2[t];
    for (int k = 0; k < D; k++) a2 = fmaf(s1[k], Wl2[k * D + t], a2);
    s2[t] = fmaxf(a2, 0.f) * Wo[t];
    __syncthreads();

    for (int off = 64; off > 0; off >>= 1) {
        if (t < off) s2[t] += s2[t + off];
        __syncthreads();
    }
    if (t == 0) out[0] = s2[0] + bo[0];
}

// Tail cleanup: re-zero scratch for the NEXT graph replay (globals start zeroed
// at module load, so the first call is also correct).
__global__ void k_clean(int n) {
    int i = blockIdx.x * blockDim.x + threadIdx.x;
    if (i < n) { g_deg_out[i] = 0; g_deg_in[i] = 0; g_cursor[i] = 0; }
    if (i < D) g_colsum[i] = 0.0f;
    if (i < 256) g_bflag[i] = 0;
}

// ================= launch =========================================================
extern "C" void kernel_launch(void* const* d_in, const int* in_sizes, int n_in,
                              void* d_out, int out_size) {
    const float* x   = (const float*)d_in[0];
    const int*   src = (const int*)  d_in[1];
    const int*   dst = (const int*)  d_in[2];
    const float* W1  = (const float*)d_in[3];
    const float* b1  = (const float*)d_in[4];
    const float* W2  = (const float*)d_in[5];
    const float* b2  = (const float*)d_in[6];
    const float* W3  = (const float*)d_in[7];
    const float* b3  = (const float*)d_in[8];
    const float* W4  = (const float*)d_in[9];
    const float* b4  = (const float*)d_in[10];
    const float* Wl1 = (const float*)d_in[11];
    const float* bl1 = (const float*)d_in[12];
    const float* Wl2 = (const float*)d_in[13];
    const float* bl2 = (const float*)d_in[14];
    const float* Wo  = (const float*)d_in[15];
    const float* bo  = (const float*)d_in[16];
    float* out = (float*)d_out;

    int n = in_sizes[0] / D;
    int e = in_sizes[1];

    cudaFuncSetAttribute(k_gemm_mma, cudaFuncAttributeMaxDynamicSharedMemorySize,
                         GM_SMEM);

    float *h, *h2;
    __nv_bfloat16* t;
    uint4* wf;
    cudaGetSymbolAddress((void**)&h,  g_h);
    cudaGetSymbolAddress((void**)&h2, g_h2);
    cudaGetSymbolAddress((void**)&t,  g_t);
    cudaGetSymbolAddress((void**)&wf, g_wfrag);

    int nb = (n + SCAN_B - 1) / SCAN_B;
    int ntiles = (n + 127) / 128;
    int ggrid  = ntiles < 296 ? ntiles : 296;
    int agg_grid = (n * 16 + 255) / 256;

    // launch order: gemm layer 1 sits at index 3 (ncu's empirical capture slot)
    k_deg   <<<(e + 255) / 256, 256>>>(src, dst, e);                 // 0
    k_scanf <<<nb, SCAN_B>>>(n);                                     // 1
    k_fillw <<<(e + 255) / 256, 256>>>(src, dst, e, W1, W2, W3, W4); // 2

    // layer 1: x -> h
    k_gemm_mma<<<ggrid, 256, GM_SMEM>>>(x, wf + 0 * 2048, t, n, ntiles); // 3 <- ncu
    k_agg     <<<agg_grid, 256>>>(t, b1, h, n, 0);
    // layer 2: h -> h2
    k_gemm_mma<<<ggrid, 256, GM_SMEM>>>(h, wf + 1 * 2048, t, n, ntiles);
    k_agg     <<<agg_grid, 256>>>(t, b2, h2, n, 0);
    // layer 3: h2 -> h
    k_gemm_mma<<<ggrid, 256, GM_SMEM>>>(h2, wf + 2 * 2048, t, n, ntiles);
    k_agg     <<<agg_grid, 256>>>(t, b3, h, n, 0);
    // layer 4: h -> h2 (fused column-sum for the mean)
    k_gemm_mma<<<ggrid, 256, GM_SMEM>>>(h, wf + 3 * 2048, t, n, ntiles);
    k_agg     <<<agg_grid, 256>>>(t, b4, h2, n, 1);

    k_mlp  <<<1, D>>>(Wl1, bl1, Wl2, bl2, Wo, bo, out, n);
    k_clean<<<(n + 255) / 256, 256>>>(n);
}

// round 9
// speedup vs baseline: 1.6857x; 1.2019x over previous
#include <cuda_runtime.h>
#include <cuda_bf16.h>
#include <cstdint>

// Problem constants: N=100000 nodes, E=1.6M edges, D=128.
#define NMAX 100000
#define EMAX 1600000
#define D 128
#define SCAN_B 1024

// ================= scratch (static device globals; zero at module load) ===========
__device__ int   g_deg_out[NMAX];
__device__ int   g_deg_in [NMAX];
__device__ float g_inv_out[NMAX];
__device__ float g_inv_in [NMAX];
__device__ int   g_row_off[NMAX + 1];
__device__ int   g_cursor [NMAX];
__device__ int   g_csr    [EMAX];
__device__ int   g_bsum   [256];
__device__ int   g_bflag  [256];
__device__ __nv_bfloat16 g_hb[(size_t)NMAX * D];  // gemm input (pre-scaled by inv_out)
__device__ __nv_bfloat16 g_t [(size_t)NMAX * D];  // gemm output / gather tensor
__device__ float g_colsum [D];
// W fragments per layer (bf16 m16n8k16): [kit(8)][nt2(8)][lane(32)] x uint4
__device__ uint4 g_wfrag  [4 * 2048];

__device__ __forceinline__ uint32_t pk_bf16x2(float lo, float hi) {
    __nv_bfloat162 t = __floats2bfloat162_rn(lo, hi);
    return *(uint32_t*)&t;
}

// m16n8k16 bf16 MMA, fp32 accumulate in place
__device__ __forceinline__ void mma_bf16(float* c, uint32_t a0, uint32_t a1,
                                         uint32_t a2, uint32_t a3,
                                         uint32_t b0, uint32_t b1) {
    asm volatile(
        "mma.sync.aligned.m16n8k16.row.col.f32.bf16.bf16.f32 "
        "{%0,%1,%2,%3}, {%4,%5,%6,%7}, {%8,%9}, {%0,%1,%2,%3};"
        : "+f"(c[0]), "+f"(c[1]), "+f"(c[2]), "+f"(c[3])
        : "r"(a0), "r"(a1), "r"(a2), "r"(a3), "r"(b0), "r"(b1));
}

// ================= setup kernels ==================================================
__global__ void k_deg(const int* __restrict__ src, const int* __restrict__ dst, int e) {
    int i = blockIdx.x * blockDim.x + threadIdx.x;
    if (i < e) {
        atomicAdd(&g_deg_out[src[i]], 1);
        atomicAdd(&g_deg_in [dst[i]], 1);
    }
}

// Fused: inv_sqrt degrees + full prefix scan of deg_in (decoupled aggregates).
// All 98 blocks co-resident (<= #SMs): publish aggregate BEFORE spinning.
__global__ void k_scanf(int n) {
    __shared__ int ssc[SCAN_B];
    __shared__ int swr[32];
    int t = threadIdx.x;
    int i = blockIdx.x * SCAN_B + t;

    if (i < n) {
        g_inv_out[i] = rsqrtf((float)max(g_deg_out[i], 1));
        g_inv_in [i] = rsqrtf((float)max(g_deg_in [i], 1));
    }

    int v = (i < n) ? g_deg_in[i] : 0;
    ssc[t] = v;
    __syncthreads();
    for (int off = 1; off < SCAN_B; off <<= 1) {
        int x = 0;
        if (t >= off) x = ssc[t - off];
        __syncthreads();
        ssc[t] += x;
        __syncthreads();
    }

    if (t == SCAN_B - 1) {
        g_bsum[blockIdx.x] = ssc[t];
        __threadfence();
        atomicExch(&g_bflag[blockIdx.x], 1);
    }

    int part = 0;
    if (t < blockIdx.x) {
        while (((volatile int*)g_bflag)[t] == 0) {}
        part = ((volatile int*)g_bsum)[t];
    }
    #pragma unroll
    for (int off = 16; off > 0; off >>= 1)
        part += __shfl_down_sync(0xffffffffu, part, off);
    if ((t & 31) == 0) swr[t >> 5] = part;
    __syncthreads();
    if (t < 32) {
        int p = swr[t];
        #pragma unroll
        for (int off = 16; off > 0; off >>= 1)
            p += __shfl_down_sync(0xffffffffu, p, off);
        if (t == 0) swr[0] = p;
    }
    __syncthreads();
    int offset = swr[0];

    if (i < n) g_row_off[i + 1] = ssc[t] + offset;
    if (i == 0) g_row_off[0] = 0;
}

// Fused: CSR fill + x prescale (x*inv_out -> bf16 g_hb) + W fragment packing.
__global__ void k_fillw(const int* __restrict__ src, const int* __restrict__ dst, int e,
                        const float* __restrict__ x, int n,
                        const float* __restrict__ W1, const float* __restrict__ W2,
                        const float* __restrict__ W3, const float* __restrict__ W4) {
    int gid = blockIdx.x * blockDim.x + threadIdx.x;
    int stride = gridDim.x * blockDim.x;

    if (gid < e) {
        int d = dst[gid];
        int p = g_row_off[d] + atomicAdd(&g_cursor[d], 1);
        g_csr[p] = src[gid];
    }

    // prescale x: each float4 -> bf16x4 (uint2)
    const float4* x4 = (const float4*)x;
    uint2* hb2 = (uint2*)g_hb;
    int tot = n * (D / 4);
    for (int j = gid; j < tot; j += stride) {
        int r = j >> 5;
        float s = g_inv_out[r];
        float4 v = x4[j];
        uint2 u;
        u.x = pk_bf16x2(v.x * s, v.y * s);
        u.y = pk_bf16x2(v.z * s, v.w * s);
        hb2[j] = u;
    }

    if (blockIdx.x < 4) {
        const float* W = (blockIdx.x == 0) ? W1 : (blockIdx.x == 1) ? W2
                       : (blockIdx.x == 2) ? W3 : W4;
        uint4* out = &g_wfrag[(size_t)blockIdx.x * 2048];
        for (int j = threadIdx.x; j < 2048; j += blockDim.x) {
            int lane = j & 31;
            int nt2  = (j >> 5) & 7;
            int kit  = j >> 8;             // 0..7
            int kk = kit * 16 + (lane & 3) * 2;
            int c0 = nt2 * 16 + (lane >> 2);
            uint4 v;
            v.x = pk_bf16x2(W[kk * D + c0],        W[(kk + 1) * D + c0]);
            v.y = pk_bf16x2(W[(kk + 8) * D + c0],  W[(kk + 9) * D + c0]);
            v.z = pk_bf16x2(W[kk * D + c0 + 8],    W[(kk + 1) * D + c0 + 8]);
            v.w = pk_bf16x2(W[(kk + 8) * D + c0 + 8], W[(kk + 9) * D + c0 + 8]);
            out[j] = v;
        }
    }
}

// ================= tensor-core GEMM: t = hb @ W (hb already scaled), bf16 =========
// mma.sync m16n8k16 bf16. CTA tile 128x128, 8 warps, warp tile 32x64.
// Whole 128x128 bf16 A tile staged per tile (one sync pair, MLP=8).
// Shared: W-frags 32KB + A tile 128 x 136 bf16 (pad keeps frag reads conflict-free).
#define GM_SW_U4 2048
#define GM_SA_OFF (GM_SW_U4 * 16)            // 32768 B
#define GM_SA_PAD 136                         // bf16 elements per row
#define GM_SMEM (GM_SA_OFF + 128 * GM_SA_PAD * 2)  // 32768 + 34816 = 67584 B

__global__ void __launch_bounds__(256, 2)
k_gemm_mma(const __nv_bfloat16* __restrict__ hin, const uint4* __restrict__ wfrag,
           __nv_bfloat16* __restrict__ tout, int n, int ntiles) {
    extern __shared__ char smem[];
    uint4* sW = (uint4*)smem;
    __nv_bfloat16* sA = (__nv_bfloat16*)(smem + GM_SA_OFF);

    int tid = threadIdx.x;
    int w = tid >> 5, lane = tid & 31;
    int qr = lane >> 2;        // 0..7
    int qc = lane & 3;         // 0..3
    int mrow = (w & 3) * 32;   // warp row base within tile
    int nc2_0 = (w >> 2) * 4;  // warp nt2 base (cols (w>>2)*64)
    int ncol = (w >> 2) * 64;

    // stage W fragments once per persistent CTA
    for (int i = tid; i < GM_SW_U4; i += 256) sW[i] = wfrag[i];

    for (int tile = blockIdx.x; tile < ntiles; tile += gridDim.x) {
        int row0 = tile * 128;

        __syncthreads();   // prior tile's sA reads done (also fences sW load, 1st iter)
        // stage WHOLE A tile: 128 rows x 128 bf16 = 2048 uint4, 8 per thread,
        // all independent loads -> deep MLP, coalesced 128B per 8 threads.
        #pragma unroll
        for (int i = tid; i < 2048; i += 256) {
            int r   = i >> 4;
            int c16 = i & 15;
            int gr = row0 + r;
            uint4 u = make_uint4(0u, 0u, 0u, 0u);
            if (gr < n) u = *(const uint4*)&hin[(size_t)gr * D + c16 * 8];
            *(uint4*)&sA[r * GM_SA_PAD + c16 * 8] = u;
        }
        __syncthreads();

        float acc[2][8][4];
        #pragma unroll
        for (int s = 0; s < 2; s++)
            #pragma unroll
            for (int nt = 0; nt < 8; nt++)
                #pragma unroll
                for (int j = 0; j < 4; j++) acc[s][nt][j] = 0.0f;

        #pragma unroll
        for (int kitg = 0; kitg < 8; kitg++) {
            int kb = kitg * 16 + qc * 2;
            uint32_t a[2][4];
            #pragma unroll
            for (int s = 0; s < 2; s++) {
                int r0 = mrow + s * 16 + qr;
                a[s][0] = *(const uint32_t*)&sA[r0 * GM_SA_PAD + kb];
                a[s][1] = *(const uint32_t*)&sA[(r0 + 8) * GM_SA_PAD + kb];
                a[s][2] = *(const uint32_t*)&sA[r0 * GM_SA_PAD + kb + 8];
                a[s][3] = *(const uint32_t*)&sA[(r0 + 8) * GM_SA_PAD + kb + 8];
            }
            #pragma unroll
            for (int i = 0; i < 4; i++) {
                uint4 bb = sW[(kitg * 8 + nc2_0 + i) * 32 + lane];
                #pragma unroll
                for (int s = 0; s < 2; s++) {
                    mma_bf16(acc[s][2 * i],
                             a[s][0], a[s][1], a[s][2], a[s][3], bb.x, bb.y);
                    mma_bf16(acc[s][2 * i + 1],
                             a[s][0], a[s][1], a[s][2], a[s][3], bb.z, bb.w);
                }
            }
        }

        // epilogue: pack fp32 pairs -> bf16x2
        #pragma unroll
        for (int s = 0; s < 2; s++) {
            int r0g = row0 + mrow + s * 16 + qr;
            int r1g = r0g + 8;
            #pragma unroll
            for (int nt = 0; nt < 8; nt++) {
                int col = ncol + nt * 8 + qc * 2;
                if (r0g < n) {
                    __nv_bfloat162 o = __floats2bfloat162_rn(acc[s][nt][0], acc[s][nt][1]);
                    *(__nv_bfloat162*)&tout[(size_t)r0g * D + col] = o;
                }
                if (r1g < n) {
                    __nv_bfloat162 o = __floats2bfloat162_rn(acc[s][nt][2], acc[s][nt][3]);
                    *(__nv_bfloat162*)&tout[(size_t)r1g * D + col] = o;
                }
            }
        }
    }
}

// ================= aggregation: half-warp per node, LDG.128 gathers ===============
// Layers 1-3 (last=0): write next gemm input = bf16(inv_out * relu(...)).
// Layer 4 (last=1): no store; only fused column-sum for the graph mean.
__device__ __forceinline__ void acc8(uint4 v, float* a) {
    float2 f0 = __bfloat1622float2(*(__nv_bfloat162*)&v.x);
    float2 f1 = __bfloat1622float2(*(__nv_bfloat162*)&v.y);
    float2 f2 = __bfloat1622float2(*(__nv_bfloat162*)&v.z);
    float2 f3 = __bfloat1622float2(*(__nv_bfloat162*)&v.w);
    a[0] += f0.x; a[1] += f0.y; a[2] += f1.x; a[3] += f1.y;
    a[4] += f2.x; a[5] += f2.y; a[6] += f3.x; a[7] += f3.y;
}

__global__ void __launch_bounds__(256)
k_agg(const __nv_bfloat16* __restrict__ tin, const float* __restrict__ bias,
      __nv_bfloat16* __restrict__ hbout, int n, int last) {
    __shared__ float sCol[D];
    int tid = threadIdx.x;
    if (last) {
        if (tid < D) sCol[tid] = 0.0f;
        __syncthreads();
    }

    int hw = (blockIdx.x * blockDim.x + tid) >> 4;   // half-warp = node
    int lane16 = tid & 15;
    int halfsel = tid & 16;
    bool active = hw < n;
    int s = 0, deg = 0;
    if (active) { s = g_row_off[hw]; deg = g_row_off[hw + 1] - s; }
    int coff = lane16 * 8;                            // bf16 col offset (16B)

    float a[8];
    #pragma unroll
    for (int j = 0; j < 8; j++) a[j] = 0.0f;

    for (int base = 0; __any_sync(0xffffffffu, base < deg); base += 16) {
        int m = deg - base;
        m = (m < 0) ? 0 : (m > 16 ? 16 : m);
        int idx = 0;
        if (lane16 < m) idx = g_csr[s + base + lane16];

        #pragma unroll
        for (int jb = 0; jb < 16; jb += 8) {
            int i0 = __shfl_sync(0xffffffffu, idx, halfsel + jb + 0);
            int i1 = __shfl_sync(0xffffffffu, idx, halfsel + jb + 1);
            int i2 = __shfl_sync(0xffffffffu, idx, halfsel + jb + 2);
            int i3 = __shfl_sync(0xffffffffu, idx, halfsel + jb + 3);
            int i4 = __shfl_sync(0xffffffffu, idx, halfsel + jb + 4);
            int i5 = __shfl_sync(0xffffffffu, idx, halfsel + jb + 5);
            int i6 = __shfl_sync(0xffffffffu, idx, halfsel + jb + 6);
            int i7 = __shfl_sync(0xffffffffu, idx, halfsel + jb + 7);
            uint4 z = make_uint4(0u, 0u, 0u, 0u);
            uint4 v0 = z, v1 = z, v2 = z, v3 = z, v4 = z, v5 = z, v6 = z, v7 = z;
            if (jb + 0 < m) v0 = *(const uint4*)&tin[(size_t)i0 * D + coff];
            if (jb + 1 < m) v1 = *(const uint4*)&tin[(size_t)i1 * D + coff];
            if (jb + 2 < m) v2 = *(const uint4*)&tin[(size_t)i2 * D + coff];
            if (jb + 3 < m) v3 = *(const uint4*)&tin[(size_t)i3 * D + coff];
            if (jb + 4 < m) v4 = *(const uint4*)&tin[(size_t)i4 * D + coff];
            if (jb + 5 < m) v5 = *(const uint4*)&tin[(size_t)i5 * D + coff];
            if (jb + 6 < m) v6 = *(const uint4*)&tin[(size_t)i6 * D + coff];
            if (jb + 7 < m) v7 = *(const uint4*)&tin[(size_t)i7 * D + coff];
            acc8(v0, a); acc8(v1, a); acc8(v2, a); acc8(v3, a);
            acc8(v4, a); acc8(v5, a); acc8(v6, a); acc8(v7, a);
        }
    }

    if (active) {
        float inv = g_inv_in[hw];
        float o[8];
        #pragma unroll
        for (int j = 0; j < 8; j++)
            o[j] = fmaxf(fmaf(a[j], inv, bias[coff + j]), 0.f);

        if (!last) {
            float so = g_inv_out[hw];   // pre-scale for the next gemm
            uint4 u;
            u.x = pk_bf16x2(o[0] * so, o[1] * so);
            u.y = pk_bf16x2(o[2] * so, o[3] * so);
            u.z = pk_bf16x2(o[4] * so, o[5] * so);
            u.w = pk_bf16x2(o[6] * so, o[7] * so);
            *(uint4*)&hbout[(size_t)hw * D + coff] = u;
        } else {
            #pragma unroll
            for (int j = 0; j < 8; j++) atomicAdd(&sCol[coff + j], o[j]);
        }
    }

    if (last) {
        __syncthreads();
        if (tid < D) atomicAdd(&g_colsum[tid], sCol[tid]);
    }
}

// ================= epilogue =======================================================
__global__ void k_mlp(const float* __restrict__ Wl1, const float* __restrict__ bl1,
                      const float* __restrict__ Wl2, const float* __restrict__ bl2,
                      const float* __restrict__ Wo,  const float* __restrict__ bo,
                      float* __restrict__ out, int n) {
    __shared__ float s0[D], s1[D], s2[D];
    int t = threadIdx.x;
    s0[t] = g_colsum[t] * (1.0f / (float)n);
    __syncthreads();

    float a = bl1[t];
    for (int k = 0; k < D; k++) a = fmaf(s0[k], Wl1[k * D + t], a);
    s1[t] = fmaxf(a, 0.f);
    __syncthreads();

    float a2 = bl2[t];
    for (int k = 0; k < D; k++) a2 = fmaf(s1[k], Wl2[k * D + t], a2);
    s2[t] = fmaxf(a2, 0.f) * Wo[t];
    __syncthreads();

    for (int off = 64; off > 0; off >>= 1) {
        if (t < off) s2[t] += s2[t + off];
        __syncthreads();
    }
    if (t == 0) out[0] = s2[0] + bo[0];
}

// Tail cleanup: re-zero scratch for the NEXT graph replay (globals start zeroed
// at module load, so the first call is also correct).
__global__ void k_clean(int n) {
    int i = blockIdx.x * blockDim.x + threadIdx.x;
    if (i < n) { g_deg_out[i] = 0; g_deg_in[i] = 0; g_cursor[i] = 0; }
    if (i < D) g_colsum[i] = 0.0f;
    if (i < 256) g_bflag[i] = 0;
}

// ================= launch =========================================================
extern "C" void kernel_launch(void* const* d_in, const int* in_sizes, int n_in,
                              void* d_out, int out_size) {
    const float* x   = (const float*)d_in[0];
    const int*   src = (const int*)  d_in[1];
    const int*   dst = (const int*)  d_in[2];
    const float* W1  = (const float*)d_in[3];
    const float* b1  = (const float*)d_in[4];
    const float* W2  = (const float*)d_in[5];
    const float* b2  = (const float*)d_in[6];
    const float* W3  = (const float*)d_in[7];
    const float* b3  = (const float*)d_in[8];
    const float* W4  = (const float*)d_in[9];
    const float* b4  = (const float*)d_in[10];
    const float* Wl1 = (const float*)d_in[11];
    const float* bl1 = (const float*)d_in[12];
    const float* Wl2 = (const float*)d_in[13];
    const float* bl2 = (const float*)d_in[14];
    const float* Wo  = (const float*)d_in[15];
    const float* bo  = (const float*)d_in[16];
    float* out = (float*)d_out;

    int n = in_sizes[0] / D;
    int e = in_sizes[1];

    cudaFuncSetAttribute(k_gemm_mma, cudaFuncAttributeMaxDynamicSharedMemorySize,
                         GM_SMEM);

    __nv_bfloat16 *hb, *t;
    uint4* wf;
    cudaGetSymbolAddress((void**)&hb, g_hb);
    cudaGetSymbolAddress((void**)&t,  g_t);
    cudaGetSymbolAddress((void**)&wf, g_wfrag);

    int nb = (n + SCAN_B - 1) / SCAN_B;
    int ntiles = (n + 127) / 128;
    int ggrid  = ntiles < 296 ? ntiles : 296;
    int agg_grid = (n * 16 + 255) / 256;

    // launch order: gemm layer 1 sits at index 3 (ncu's empirical capture slot)
    k_deg   <<<(e + 255) / 256, 256>>>(src, dst, e);                    // 0
    k_scanf <<<nb, SCAN_B>>>(n);                                        // 1
    k_fillw <<<(e + 255) / 256, 256>>>(src, dst, e, x, n, W1, W2, W3, W4); // 2

    // layer 1
    k_gemm_mma<<<ggrid, 256, GM_SMEM>>>(hb, wf + 0 * 2048, t, n, ntiles); // 3 <- ncu
    k_agg     <<<agg_grid, 256>>>(t, b1, hb, n, 0);
    // layer 2
    k_gemm_mma<<<ggrid, 256, GM_SMEM>>>(hb, wf + 1 * 2048, t, n, ntiles);
    k_agg     <<<agg_grid, 256>>>(t, b2, hb, n, 0);
    // layer 3
    k_gemm_mma<<<ggrid, 256, GM_SMEM>>>(hb, wf + 2 * 2048, t, n, ntiles);
    k_agg     <<<agg_grid, 256>>>(t, b3, hb, n, 0);
    // layer 4 (column-sum only)
    k_gemm_mma<<<ggrid, 256, GM_SMEM>>>(hb, wf + 3 * 2048, t, n, ntiles);
    k_agg     <<<agg_grid, 256>>>(t, b4, hb, n, 1);

    k_mlp  <<<1, D>>>(Wl1, bl1, Wl2, bl2, Wo, bo, out, n);
    k_clean<<<(n + 255) / 256, 256>>>(n);
}

// round 10
// speedup vs baseline: 1.7062x; 1.0122x over previous
#include <cuda_runtime.h>
#include <cuda_bf16.h>
#include <cstdint>

// Problem constants: N=100000 nodes, E=1.6M edges, D=128.
#define NMAX 100000
#define EMAX 1600000
#define D 128
#define SCAN_B 1024

// ================= scratch (static device globals; zero at module load) ===========
__device__ int   g_deg_out[NMAX];
__device__ int   g_deg_in [NMAX];
__device__ float g_inv_out[NMAX];
__device__ float g_inv_in [NMAX];
__device__ int   g_row_off[NMAX + 1];
__device__ int   g_cursor [NMAX];
__device__ int   g_csr    [EMAX];
__device__ int   g_bsum   [256];
__device__ int   g_bflag  [256];
__device__ __nv_bfloat16 g_hb[(size_t)NMAX * D];  // gemm input (pre-scaled by inv_out)
__device__ __nv_bfloat16 g_t [(size_t)NMAX * D];  // gemm output / gather tensor
__device__ float g_colsum [D];
// W fragments per layer (bf16 m16n8k16): [kit(8)][nt2(8)][lane(32)] x uint4
__device__ uint4 g_wfrag  [4 * 2048];

__device__ __forceinline__ uint32_t pk_bf16x2(float lo, float hi) {
    __nv_bfloat162 t = __floats2bfloat162_rn(lo, hi);
    return *(uint32_t*)&t;
}

// m16n8k16 bf16 MMA, fp32 accumulate in place
__device__ __forceinline__ void mma_bf16(float* c, uint32_t a0, uint32_t a1,
                                         uint32_t a2, uint32_t a3,
                                         uint32_t b0, uint32_t b1) {
    asm volatile(
        "mma.sync.aligned.m16n8k16.row.col.f32.bf16.bf16.f32 "
        "{%0,%1,%2,%3}, {%4,%5,%6,%7}, {%8,%9}, {%0,%1,%2,%3};"
        : "+f"(c[0]), "+f"(c[1]), "+f"(c[2]), "+f"(c[3])
        : "r"(a0), "r"(a1), "r"(a2), "r"(a3), "r"(b0), "r"(b1));
}

// cp.async 16B global->shared; src_size=0 zero-fills (for out-of-range rows)
__device__ __forceinline__ void cp_async16(uint32_t saddr, const void* gptr, bool pred) {
    int sz = pred ? 16 : 0;
    asm volatile("cp.async.cg.shared.global [%0], [%1], 16, %2;"
                 :: "r"(saddr), "l"(gptr), "r"(sz));
}
#define CP_COMMIT() asm volatile("cp.async.commit_group;" ::: "memory")
#define CP_WAIT0()  asm volatile("cp.async.wait_group 0;" ::: "memory")
#define CP_WAIT1()  asm volatile("cp.async.wait_group 1;" ::: "memory")

// ================= setup kernels ==================================================
__global__ void k_deg(const int* __restrict__ src, const int* __restrict__ dst, int e) {
    int i = blockIdx.x * blockDim.x + threadIdx.x;
    if (i < e) {
        atomicAdd(&g_deg_out[src[i]], 1);
        atomicAdd(&g_deg_in [dst[i]], 1);
    }
}

// Fused: inv_sqrt degrees + full prefix scan of deg_in (decoupled aggregates).
// All 98 blocks co-resident (<= #SMs): publish aggregate BEFORE spinning.
__global__ void k_scanf(int n) {
    __shared__ int ssc[SCAN_B];
    __shared__ int swr[32];
    int t = threadIdx.x;
    int i = blockIdx.x * SCAN_B + t;

    if (i < n) {
        g_inv_out[i] = rsqrtf((float)max(g_deg_out[i], 1));
        g_inv_in [i] = rsqrtf((float)max(g_deg_in [i], 1));
    }

    int v = (i < n) ? g_deg_in[i] : 0;
    ssc[t] = v;
    __syncthreads();
    for (int off = 1; off < SCAN_B; off <<= 1) {
        int x = 0;
        if (t >= off) x = ssc[t - off];
        __syncthreads();
        ssc[t] += x;
        __syncthreads();
    }

    if (t == SCAN_B - 1) {
        g_bsum[blockIdx.x] = ssc[t];
        __threadfence();
        atomicExch(&g_bflag[blockIdx.x], 1);
    }

    int part = 0;
    if (t < blockIdx.x) {
        while (((volatile int*)g_bflag)[t] == 0) {}
        part = ((volatile int*)g_bsum)[t];
    }
    #pragma unroll
    for (int off = 16; off > 0; off >>= 1)
        part += __shfl_down_sync(0xffffffffu, part, off);
    if ((t & 31) == 0) swr[t >> 5] = part;
    __syncthreads();
    if (t < 32) {
        int p = swr[t];
        #pragma unroll
        for (int off = 16; off > 0; off >>= 1)
            p += __shfl_down_sync(0xffffffffu, p, off);
        if (t == 0) swr[0] = p;
    }
    __syncthreads();
    int offset = swr[0];

    if (i < n) g_row_off[i + 1] = ssc[t] + offset;
    if (i == 0) g_row_off[0] = 0;
}

// Fused: CSR fill + x prescale (x*inv_out -> bf16 g_hb) + W fragment packing.
__global__ void k_fillw(const int* __restrict__ src, const int* __restrict__ dst, int e,
                        const float* __restrict__ x, int n,
                        const float* __restrict__ W1, const float* __restrict__ W2,
                        const float* __restrict__ W3, const float* __restrict__ W4) {
    int gid = blockIdx.x * blockDim.x + threadIdx.x;
    int stride = gridDim.x * blockDim.x;

    if (gid < e) {
        int d = dst[gid];
        int p = g_row_off[d] + atomicAdd(&g_cursor[d], 1);
        g_csr[p] = src[gid];
    }

    // prescale x: each float4 -> bf16x4 (uint2)
    const float4* x4 = (const float4*)x;
    uint2* hb2 = (uint2*)g_hb;
    int tot = n * (D / 4);
    for (int j = gid; j < tot; j += stride) {
        int r = j >> 5;
        float s = g_inv_out[r];
        float4 v = x4[j];
        uint2 u;
        u.x = pk_bf16x2(v.x * s, v.y * s);
        u.y = pk_bf16x2(v.z * s, v.w * s);
        hb2[j] = u;
    }

    if (blockIdx.x < 4) {
        const float* W = (blockIdx.x == 0) ? W1 : (blockIdx.x == 1) ? W2
                       : (blockIdx.x == 2) ? W3 : W4;
        uint4* out = &g_wfrag[(size_t)blockIdx.x * 2048];
        for (int j = threadIdx.x; j < 2048; j += blockDim.x) {
            int lane = j & 31;
            int nt2  = (j >> 5) & 7;
            int kit  = j >> 8;             // 0..7
            int kk = kit * 16 + (lane & 3) * 2;
            int c0 = nt2 * 16 + (lane >> 2);
            uint4 v;
            v.x = pk_bf16x2(W[kk * D + c0],        W[(kk + 1) * D + c0]);
            v.y = pk_bf16x2(W[(kk + 8) * D + c0],  W[(kk + 9) * D + c0]);
            v.z = pk_bf16x2(W[kk * D + c0 + 8],    W[(kk + 1) * D + c0 + 8]);
            v.w = pk_bf16x2(W[(kk + 8) * D + c0 + 8], W[(kk + 9) * D + c0 + 8]);
            out[j] = v;
        }
    }
}

// ================= tensor-core GEMM: t = hb @ W (hb already scaled), bf16 =========
// mma.sync m16n8k16 bf16. CTA tile 128x128, 8 warps, warp tile 32x64.
// Double-buffered A tiles staged via cp.async; next tile prefetched during mma.
// Shared: W-frags 32KB + 2 x (128 x 136 bf16) A buffers.
#define GM_SW_U4 2048
#define GM_SA_OFF (GM_SW_U4 * 16)            // 32768 B
#define GM_SA_PAD 136                         // bf16 elements per row
#define GM_SA_BYTES (128 * GM_SA_PAD * 2)     // 34816 B per buffer
#define GM_SMEM (GM_SA_OFF + 2 * GM_SA_BYTES) // 32768 + 69632 = 102400 B

__global__ void __launch_bounds__(256, 2)
k_gemm_mma(const __nv_bfloat16* __restrict__ hin, const uint4* __restrict__ wfrag,
           __nv_bfloat16* __restrict__ tout, int n, int ntiles) {
    extern __shared__ char smem[];
    uint4* sW = (uint4*)smem;
    uint32_t sA_u32 = (uint32_t)__cvta_generic_to_shared(smem + GM_SA_OFF);

    int tid = threadIdx.x;
    int w = tid >> 5, lane = tid & 31;
    int qr = lane >> 2;        // 0..7
    int qc = lane & 3;         // 0..3
    int mrow = (w & 3) * 32;   // warp row base within tile
    int nc2_0 = (w >> 2) * 4;  // warp nt2 base (cols (w>>2)*64)
    int ncol = (w >> 2) * 64;

    // stage W fragments once per persistent CTA
    for (int i = tid; i < GM_SW_U4; i += 256) sW[i] = wfrag[i];

    // per-thread staging pattern: 8 x 16B, row r = i>>4, col chunk c16 = i&15
    int st_r   = tid >> 4;           // rows tid/16 .. +16 step (8 iters over i)
    int st_c16 = tid & 15;

    // prefetch first tile into buffer 0
    {
        int row0 = blockIdx.x * 128;
        #pragma unroll
        for (int k = 0; k < 8; k++) {
            int r = st_r + k * 16;
            int gr = row0 + r;
            cp_async16(sA_u32 + (uint32_t)(r * GM_SA_PAD + st_c16 * 8) * 2,
                       &hin[(size_t)gr * D + st_c16 * 8], gr < n);
        }
        CP_COMMIT();
    }

    int buf = 0;
    for (int tile = blockIdx.x; tile < ntiles; tile += gridDim.x) {
        int row0 = tile * 128;
        int ntile = tile + gridDim.x;

        if (ntile < ntiles) {
            // prefetch next tile into the other buffer
            int nrow0 = ntile * 128;
            uint32_t nb = sA_u32 + (buf ^ 1) * GM_SA_BYTES;
            #pragma unroll
            for (int k = 0; k < 8; k++) {
                int r = st_r + k * 16;
                int gr = nrow0 + r;
                cp_async16(nb + (uint32_t)(r * GM_SA_PAD + st_c16 * 8) * 2,
                           &hin[(size_t)gr * D + st_c16 * 8], gr < n);
            }
            CP_COMMIT();
            CP_WAIT1();   // current tile's group complete (1 newer pending)
        } else {
            CP_WAIT0();
        }
        __syncthreads();

        const __nv_bfloat16* sA =
            (const __nv_bfloat16*)(smem + GM_SA_OFF + buf * GM_SA_BYTES);

        float acc[2][8][4];
        #pragma unroll
        for (int s = 0; s < 2; s++)
            #pragma unroll
            for (int nt = 0; nt < 8; nt++)
                #pragma unroll
                for (int j = 0; j < 4; j++) acc[s][nt][j] = 0.0f;

        #pragma unroll
        for (int kitg = 0; kitg < 8; kitg++) {
            int kb = kitg * 16 + qc * 2;
            uint32_t a[2][4];
            #pragma unroll
            for (int s = 0; s < 2; s++) {
                int r0 = mrow + s * 16 + qr;
                a[s][0] = *(const uint32_t*)&sA[r0 * GM_SA_PAD + kb];
                a[s][1] = *(const uint32_t*)&sA[(r0 + 8) * GM_SA_PAD + kb];
                a[s][2] = *(const uint32_t*)&sA[r0 * GM_SA_PAD + kb + 8];
                a[s][3] = *(const uint32_t*)&sA[(r0 + 8) * GM_SA_PAD + kb + 8];
            }
            #pragma unroll
            for (int i = 0; i < 4; i++) {
                uint4 bb = sW[(kitg * 8 + nc2_0 + i) * 32 + lane];
                #pragma unroll
                for (int s = 0; s < 2; s++) {
                    mma_bf16(acc[s][2 * i],
                             a[s][0], a[s][1], a[s][2], a[s][3], bb.x, bb.y);
                    mma_bf16(acc[s][2 * i + 1],
                             a[s][0], a[s][1], a[s][2], a[s][3], bb.z, bb.w);
                }
            }
        }

        // epilogue: pack fp32 pairs -> bf16x2
        #pragma unroll
        for (int s = 0; s < 2; s++) {
            int r0g = row0 + mrow + s * 16 + qr;
            int r1g = r0g + 8;
            #pragma unroll
            for (int nt = 0; nt < 8; nt++) {
                int col = ncol + nt * 8 + qc * 2;
                if (r0g < n) {
                    __nv_bfloat162 o = __floats2bfloat162_rn(acc[s][nt][0], acc[s][nt][1]);
                    *(__nv_bfloat162*)&tout[(size_t)r0g * D + col] = o;
                }
                if (r1g < n) {
                    __nv_bfloat162 o = __floats2bfloat162_rn(acc[s][nt][2], acc[s][nt][3]);
                    *(__nv_bfloat162*)&tout[(size_t)r1g * D + col] = o;
                }
            }
        }

        __syncthreads();   // all reads of sA[buf] done before it is prefetch-overwritten
        buf ^= 1;
    }
}

// ================= aggregation: half-warp per node, LDG.128 gathers ===============
// Layers 1-3 (last=0): write next gemm input = bf16(inv_out * relu(...)).
// Layer 4 (last=1): no store; only fused column-sum for the graph mean.
__device__ __forceinline__ void acc8(uint4 v, float* a) {
    float2 f0 = __bfloat1622float2(*(__nv_bfloat162*)&v.x);
    float2 f1 = __bfloat1622float2(*(__nv_bfloat162*)&v.y);
    float2 f2 = __bfloat1622float2(*(__nv_bfloat162*)&v.z);
    float2 f3 = __bfloat1622float2(*(__nv_bfloat162*)&v.w);
    a[0] += f0.x; a[1] += f0.y; a[2] += f1.x; a[3] += f1.y;
    a[4] += f2.x; a[5] += f2.y; a[6] += f3.x; a[7] += f3.y;
}

__global__ void __launch_bounds__(256)
k_agg(const __nv_bfloat16* __restrict__ tin, const float* __restrict__ bias,
      __nv_bfloat16* __restrict__ hbout, int n, int last) {
    __shared__ float sCol[D];
    int tid = threadIdx.x;
    if (last) {
        if (tid < D) sCol[tid] = 0.0f;
        __syncthreads();
    }

    int hw = (blockIdx.x * blockDim.x + tid) >> 4;   // half-warp = node
    int lane16 = tid & 15;
    int halfsel = tid & 16;
    bool active = hw < n;
    int s = 0, deg = 0;
    if (active) { s = g_row_off[hw]; deg = g_row_off[hw + 1] - s; }
    int coff = lane16 * 8;                            // bf16 col offset (16B)

    float a[8];
    #pragma unroll
    for (int j = 0; j < 8; j++) a[j] = 0.0f;

    for (int base = 0; __any_sync(0xffffffffu, base < deg); base += 16) {
        int m = deg - base;
        m = (m < 0) ? 0 : (m > 16 ? 16 : m);
        int idx = 0;
        if (lane16 < m) idx = g_csr[s + base + lane16];

        #pragma unroll
        for (int jb = 0; jb < 16; jb += 8) {
            int i0 = __shfl_sync(0xffffffffu, idx, halfsel + jb + 0);
            int i1 = __shfl_sync(0xffffffffu, idx, halfsel + jb + 1);
            int i2 = __shfl_sync(0xffffffffu, idx, halfsel + jb + 2);
            int i3 = __shfl_sync(0xffffffffu, idx, halfsel + jb + 3);
            int i4 = __shfl_sync(0xffffffffu, idx, halfsel + jb + 4);
            int i5 = __shfl_sync(0xffffffffu, idx, halfsel + jb + 5);
            int i6 = __shfl_sync(0xffffffffu, idx, halfsel + jb + 6);
            int i7 = __shfl_sync(0xffffffffu, idx, halfsel + jb + 7);
            uint4 z = make_uint4(0u, 0u, 0u, 0u);
            uint4 v0 = z, v1 = z, v2 = z, v3 = z, v4 = z, v5 = z, v6 = z, v7 = z;
            if (jb + 0 < m) v0 = *(const uint4*)&tin[(size_t)i0 * D + coff];
            if (jb + 1 < m) v1 = *(const uint4*)&tin[(size_t)i1 * D + coff];
            if (jb + 2 < m) v2 = *(const uint4*)&tin[(size_t)i2 * D + coff];
            if (jb + 3 < m) v3 = *(const uint4*)&tin[(size_t)i3 * D + coff];
            if (jb + 4 < m) v4 = *(const uint4*)&tin[(size_t)i4 * D + coff];
            if (jb + 5 < m) v5 = *(const uint4*)&tin[(size_t)i5 * D + coff];
            if (jb + 6 < m) v6 = *(const uint4*)&tin[(size_t)i6 * D + coff];
            if (jb + 7 < m) v7 = *(const uint4*)&tin[(size_t)i7 * D + coff];
            acc8(v0, a); acc8(v1, a); acc8(v2, a); acc8(v3, a);
            acc8(v4, a); acc8(v5, a); acc8(v6, a); acc8(v7, a);
        }
    }

    if (active) {
        float inv = g_inv_in[hw];
        float o[8];
        #pragma unroll
        for (int j = 0; j < 8; j++)
            o[j] = fmaxf(fmaf(a[j], inv, bias[coff + j]), 0.f);

        if (!last) {
            float so = g_inv_out[hw];   // pre-scale for the next gemm
            uint4 u;
            u.x = pk_bf16x2(o[0] * so, o[1] * so);
            u.y = pk_bf16x2(o[2] * so, o[3] * so);
            u.z = pk_bf16x2(o[4] * so, o[5] * so);
            u.w = pk_bf16x2(o[6] * so, o[7] * so);
            *(uint4*)&hbout[(size_t)hw * D + coff] = u;
        } else {
            #pragma unroll
            for (int j = 0; j < 8; j++) atomicAdd(&sCol[coff + j], o[j]);
        }
    }

    if (last) {
        __syncthreads();
        if (tid < D) atomicAdd(&g_colsum[tid], sCol[tid]);
    }
}

// ================= epilogue =======================================================
__global__ void k_mlp(const float* __restrict__ Wl1, const float* __restrict__ bl1,
                      const float* __restrict__ Wl2, const float* __restrict__ bl2,
                      const float* __restrict__ Wo,  const float* __restrict__ bo,
                      float* __restrict__ out, int n) {
    __shared__ float s0[D], s1[D], s2[D];
    int t = threadIdx.x;
    s0[t] = g_colsum[t] * (1.0f / (float)n);
    __syncthreads();

    float a = bl1[t];
    for (int k = 0; k < D; k++) a = fmaf(s0[k], Wl1[k * D + t], a);
    s1[t] = fmaxf(a, 0.f);
    __syncthreads();

    float a2 = bl2[t];
    for (int k = 0; k < D; k++) a2 = fmaf(s1[k], Wl2[k * D + t], a2);
    s2[t] = fmaxf(a2, 0.f) * Wo[t];
    __syncthreads();

    for (int off = 64; off > 0; off >>= 1) {
        if (t < off) s2[t] += s2[t + off];
        __syncthreads();
    }
    if (t == 0) out[0] = s2[0] + bo[0];
}

// Tail cleanup: re-zero scratch for the NEXT graph replay (globals start zeroed
// at module load, so the first call is also correct).
__global__ void k_clean(int n) {
    int i = blockIdx.x * blockDim.x + threadIdx.x;
    if (i < n) { g_deg_out[i] = 0; g_deg_in[i] = 0; g_cursor[i] = 0; }
    if (i < D) g_colsum[i] = 0.0f;
    if (i < 256) g_bflag[i] = 0;
}

// ================= launch =========================================================
extern "C" void kernel_launch(void* const* d_in, const int* in_sizes, int n_in,
                              void* d_out, int out_size) {
    const float* x   = (const float*)d_in[0];
    const int*   src = (const int*)  d_in[1];
    const int*   dst = (const int*)  d_in[2];
    const float* W1  = (const float*)d_in[3];
    const float* b1  = (const float*)d_in[4];
    const float* W2  = (const float*)d_in[5];
    const float* b2  = (const float*)d_in[6];
    const float* W3  = (const float*)d_in[7];
    const float* b3  = (const float*)d_in[8];
    const float* W4  = (const float*)d_in[9];
    const float* b4  = (const float*)d_in[10];
    const float* Wl1 = (const float*)d_in[11];
    const float* bl1 = (const float*)d_in[12];
    const float* Wl2 = (const float*)d_in[13];
    const float* bl2 = (const float*)d_in[14];
    const float* Wo  = (const float*)d_in[15];
    const float* bo  = (const float*)d_in[16];
    float* out = (float*)d_out;

    int n = in_sizes[0] / D;
    int e = in_sizes[1];

    cudaFuncSetAttribute(k_gemm_mma, cudaFuncAttributeMaxDynamicSharedMemorySize,
                         GM_SMEM);

    __nv_bfloat16 *hb, *t;
    uint4* wf;
    cudaGetSymbolAddress((void**)&hb, g_hb);
    cudaGetSymbolAddress((void**)&t,  g_t);
    cudaGetSymbolAddress((void**)&wf, g_wfrag);

    int nb = (n + SCAN_B - 1) / SCAN_B;
    int ntiles = (n + 127) / 128;
    int ggrid  = ntiles < 296 ? ntiles : 296;
    int agg_grid = (n * 16 + 255) / 256;

    // launch order: gemm layer 1 sits at index 3 (ncu's empirical capture slot)
    k_deg   <<<(e + 255) / 256, 256>>>(src, dst, e);                    // 0
    k_scanf <<<nb, SCAN_B>>>(n);                                        // 1
    k_fillw <<<(e + 255) / 256, 256>>>(src, dst, e, x, n, W1, W2, W3, W4); // 2

    // layer 1
    k_gemm_mma<<<ggrid, 256, GM_SMEM>>>(hb, wf + 0 * 2048, t, n, ntiles); // 3 <- ncu
    k_agg     <<<agg_grid, 256>>>(t, b1, hb, n, 0);
    // layer 2
    k_gemm_mma<<<ggrid, 256, GM_SMEM>>>(hb, wf + 1 * 2048, t, n, ntiles);
    k_agg     <<<agg_grid, 256>>>(t, b2, hb, n, 0);
    // layer 3
    k_gemm_mma<<<ggrid, 256, GM_SMEM>>>(hb, wf + 2 * 2048, t, n, ntiles);
    k_agg     <<<agg_grid, 256>>>(t, b3, hb, n, 0);
    // layer 4 (column-sum only)
    k_gemm_mma<<<ggrid, 256, GM_SMEM>>>(hb, wf + 3 * 2048, t, n, ntiles);
    k_agg     <<<agg_grid, 256>>>(t, b4, hb, n, 1);

    k_mlp  <<<1, D>>>(Wl1, bl1, Wl2, bl2, Wo, bo, out, n);
    k_clean<<<(n + 255) / 256, 256>>>(n);
}

// round 11
// speedup vs baseline: 1.8782x; 1.1008x over previous
#include <cuda_runtime.h>
#include <cuda_bf16.h>
#include <cuda_fp16.h>
#include <cstdint>

// Problem constants: N=100000 nodes, E=1.6M edges, D=128.
#define NMAX 100000
#define EMAX 1600000
#define D 128
#define SCAN_B 1024

// ================= scratch (static device globals; zero at module load) ===========
__device__ int   g_deg_out[NMAX];
__device__ int   g_deg_in [NMAX];
__device__ float g_inv_out[NMAX];
__device__ float g_inv_in [NMAX];
__device__ int   g_row_off[NMAX + 1];
__device__ int   g_cursor [NMAX];
__device__ int   g_csr    [EMAX];
__device__ int   g_bsum   [256];
__device__ int   g_bflag  [256];
__device__ __nv_bfloat16 g_hb[(size_t)NMAX * D];  // gemm input (pre-scaled by inv_out)
__device__ uint8_t g_t [(size_t)NMAX * D];        // e4m3 gather tensor (128B/row)
__device__ float g_colsum [D];
// W fragments per layer (bf16 m16n8k16): [kit(8)][nt2(8)][lane(32)] x uint4
__device__ uint4 g_wfrag  [4 * 2048];

__device__ __forceinline__ uint32_t pk_bf16x2(float lo, float hi) {
    __nv_bfloat162 t = __floats2bfloat162_rn(lo, hi);
    return *(uint32_t*)&t;
}

// two f32 -> packed e4m3x2 (low byte = lo)
__device__ __forceinline__ uint16_t pk_e4m3x2(float lo, float hi) {
    uint16_t r;
    asm("cvt.rn.satfinite.e4m3x2.f32 %0, %1, %2;" : "=h"(r) : "f"(hi), "f"(lo));
    return r;
}

// packed e4m3x2 -> f16x2 (low e4m3 -> low f16)
__device__ __forceinline__ __half2 e4m3x2_h2(uint16_t u) {
    uint32_t r;
    asm("cvt.rn.f16x2.e4m3x2 %0, %1;" : "=r"(r) : "h"(u));
    return *(__half2*)&r;
}

// m16n8k16 bf16 MMA, fp32 accumulate in place
__device__ __forceinline__ void mma_bf16(float* c, uint32_t a0, uint32_t a1,
                                         uint32_t a2, uint32_t a3,
                                         uint32_t b0, uint32_t b1) {
    asm volatile(
        "mma.sync.aligned.m16n8k16.row.col.f32.bf16.bf16.f32 "
        "{%0,%1,%2,%3}, {%4,%5,%6,%7}, {%8,%9}, {%0,%1,%2,%3};"
        : "+f"(c[0]), "+f"(c[1]), "+f"(c[2]), "+f"(c[3])
        : "r"(a0), "r"(a1), "r"(a2), "r"(a3), "r"(b0), "r"(b1));
}

// cp.async 16B global->shared; src_size=0 zero-fills (for out-of-range rows)
__device__ __forceinline__ void cp_async16(uint32_t saddr, const void* gptr, bool pred) {
    int sz = pred ? 16 : 0;
    asm volatile("cp.async.cg.shared.global [%0], [%1], 16, %2;"
                 :: "r"(saddr), "l"(gptr), "r"(sz));
}
#define CP_COMMIT() asm volatile("cp.async.commit_group;" ::: "memory")
#define CP_WAIT0()  asm volatile("cp.async.wait_group 0;" ::: "memory")
#define CP_WAIT1()  asm volatile("cp.async.wait_group 1;" ::: "memory")

// ================= setup kernels ==================================================
__global__ void k_deg(const int* __restrict__ src, const int* __restrict__ dst, int e) {
    int i = blockIdx.x * blockDim.x + threadIdx.x;
    if (i < e) {
        atomicAdd(&g_deg_out[src[i]], 1);
        atomicAdd(&g_deg_in [dst[i]], 1);
    }
}

// Fused: inv_sqrt degrees + full prefix scan of deg_in (decoupled aggregates).
__global__ void k_scanf(int n) {
    __shared__ int ssc[SCAN_B];
    __shared__ int swr[32];
    int t = threadIdx.x;
    int i = blockIdx.x * SCAN_B + t;

    if (i < n) {
        g_inv_out[i] = rsqrtf((float)max(g_deg_out[i], 1));
        g_inv_in [i] = rsqrtf((float)max(g_deg_in [i], 1));
    }

    int v = (i < n) ? g_deg_in[i] : 0;
    ssc[t] = v;
    __syncthreads();
    for (int off = 1; off < SCAN_B; off <<= 1) {
        int x = 0;
        if (t >= off) x = ssc[t - off];
        __syncthreads();
        ssc[t] += x;
        __syncthreads();
    }

    if (t == SCAN_B - 1) {
        g_bsum[blockIdx.x] = ssc[t];
        __threadfence();
        atomicExch(&g_bflag[blockIdx.x], 1);
    }

    int part = 0;
    if (t < blockIdx.x) {
        while (((volatile int*)g_bflag)[t] == 0) {}
        part = ((volatile int*)g_bsum)[t];
    }
    #pragma unroll
    for (int off = 16; off > 0; off >>= 1)
        part += __shfl_down_sync(0xffffffffu, part, off);
    if ((t & 31) == 0) swr[t >> 5] = part;
    __syncthreads();
    if (t < 32) {
        int p = swr[t];
        #pragma unroll
        for (int off = 16; off > 0; off >>= 1)
            p += __shfl_down_sync(0xffffffffu, p, off);
        if (t == 0) swr[0] = p;
    }
    __syncthreads();
    int offset = swr[0];

    if (i < n) g_row_off[i + 1] = ssc[t] + offset;
    if (i == 0) g_row_off[0] = 0;
}

// Fused: CSR fill + x prescale (x*inv_out -> bf16 g_hb) + W fragment packing.
__global__ void k_fillw(const int* __restrict__ src, const int* __restrict__ dst, int e,
                        const float* __restrict__ x, int n,
                        const float* __restrict__ W1, const float* __restrict__ W2,
                        const float* __restrict__ W3, const float* __restrict__ W4) {
    int gid = blockIdx.x * blockDim.x + threadIdx.x;
    int stride = gridDim.x * blockDim.x;

    if (gid < e) {
        int d = dst[gid];
        int p = g_row_off[d] + atomicAdd(&g_cursor[d], 1);
        g_csr[p] = src[gid];
    }

    // prescale x: each float4 -> bf16x4 (uint2)
    const float4* x4 = (const float4*)x;
    uint2* hb2 = (uint2*)g_hb;
    int tot = n * (D / 4);
    for (int j = gid; j < tot; j += stride) {
        int r = j >> 5;
        float s = g_inv_out[r];
        float4 v = x4[j];
        uint2 u;
        u.x = pk_bf16x2(v.x * s, v.y * s);
        u.y = pk_bf16x2(v.z * s, v.w * s);
        hb2[j] = u;
    }

    if (blockIdx.x < 4) {
        const float* W = (blockIdx.x == 0) ? W1 : (blockIdx.x == 1) ? W2
                       : (blockIdx.x == 2) ? W3 : W4;
        uint4* out = &g_wfrag[(size_t)blockIdx.x * 2048];
        for (int j = threadIdx.x; j < 2048; j += blockDim.x) {
            int lane = j & 31;
            int nt2  = (j >> 5) & 7;
            int kit  = j >> 8;             // 0..7
            int kk = kit * 16 + (lane & 3) * 2;
            int c0 = nt2 * 16 + (lane >> 2);
            uint4 v;
            v.x = pk_bf16x2(W[kk * D + c0],        W[(kk + 1) * D + c0]);
            v.y = pk_bf16x2(W[(kk + 8) * D + c0],  W[(kk + 9) * D + c0]);
            v.z = pk_bf16x2(W[kk * D + c0 + 8],    W[(kk + 1) * D + c0 + 8]);
            v.w = pk_bf16x2(W[(kk + 8) * D + c0 + 8], W[(kk + 9) * D + c0 + 8]);
            out[j] = v;
        }
    }
}

// ================= tensor-core GEMM: t = hb @ W (hb pre-scaled), e4m3 out =========
// mma.sync m16n8k16 bf16. CTA tile 128x128, 8 warps, warp tile 32x64.
// Double-buffered A via cp.async. Epilogue: e4m3 C staged in the dead A buffer,
// then fully-coalesced 16B stores (128B rows).
#define GM_SW_U4 2048
#define GM_SA_OFF (GM_SW_U4 * 16)            // 32768 B
#define GM_SA_PAD 136                         // bf16 elements per row
#define GM_SA_BYTES (128 * GM_SA_PAD * 2)     // 34816 B per buffer
#define GM_SMEM (GM_SA_OFF + 2 * GM_SA_BYTES) // 102400 B

__global__ void __launch_bounds__(256, 2)
k_gemm_mma(const __nv_bfloat16* __restrict__ hin, const uint4* __restrict__ wfrag,
           uint8_t* __restrict__ tout, int n, int ntiles) {
    extern __shared__ char smem[];
    uint4* sW = (uint4*)smem;
    uint32_t sA_u32 = (uint32_t)__cvta_generic_to_shared(smem + GM_SA_OFF);

    int tid = threadIdx.x;
    int w = tid >> 5, lane = tid & 31;
    int qr = lane >> 2;        // 0..7
    int qc = lane & 3;         // 0..3
    int mrow = (w & 3) * 32;   // warp row base within tile
    int nc2_0 = (w >> 2) * 4;  // warp nt2 base (cols (w>>2)*64)
    int ncol = (w >> 2) * 64;

    // stage W fragments once per persistent CTA
    for (int i = tid; i < GM_SW_U4; i += 256) sW[i] = wfrag[i];

    int st_r   = tid >> 4;
    int st_c16 = tid & 15;

    // prefetch first tile into buffer 0
    {
        int row0 = blockIdx.x * 128;
        #pragma unroll
        for (int k = 0; k < 8; k++) {
            int r = st_r + k * 16;
            int gr = row0 + r;
            cp_async16(sA_u32 + (uint32_t)(r * GM_SA_PAD + st_c16 * 8) * 2,
                       &hin[(size_t)gr * D + st_c16 * 8], gr < n);
        }
        CP_COMMIT();
    }

    int buf = 0;
    for (int tile = blockIdx.x; tile < ntiles; tile += gridDim.x) {
        int row0 = tile * 128;
        int ntile = tile + gridDim.x;

        if (ntile < ntiles) {
            int nrow0 = ntile * 128;
            uint32_t nb = sA_u32 + (buf ^ 1) * GM_SA_BYTES;
            #pragma unroll
            for (int k = 0; k < 8; k++) {
                int r = st_r + k * 16;
                int gr = nrow0 + r;
                cp_async16(nb + (uint32_t)(r * GM_SA_PAD + st_c16 * 8) * 2,
                           &hin[(size_t)gr * D + st_c16 * 8], gr < n);
            }
            CP_COMMIT();
            CP_WAIT1();
        } else {
            CP_WAIT0();
        }
        __syncthreads();   // (A) sA[buf] ready

        const __nv_bfloat16* sA =
            (const __nv_bfloat16*)(smem + GM_SA_OFF + buf * GM_SA_BYTES);

        float acc[2][8][4];
        #pragma unroll
        for (int s = 0; s < 2; s++)
            #pragma unroll
            for (int nt = 0; nt < 8; nt++)
                #pragma unroll
                for (int j = 0; j < 4; j++) acc[s][nt][j] = 0.0f;

        #pragma unroll
        for (int kitg = 0; kitg < 8; kitg++) {
            int kb = kitg * 16 + qc * 2;
            uint32_t a[2][4];
            #pragma unroll
            for (int s = 0; s < 2; s++) {
                int r0 = mrow + s * 16 + qr;
                a[s][0] = *(const uint32_t*)&sA[r0 * GM_SA_PAD + kb];
                a[s][1] = *(const uint32_t*)&sA[(r0 + 8) * GM_SA_PAD + kb];
                a[s][2] = *(const uint32_t*)&sA[r0 * GM_SA_PAD + kb + 8];
                a[s][3] = *(const uint32_t*)&sA[(r0 + 8) * GM_SA_PAD + kb + 8];
            }
            #pragma unroll
            for (int i = 0; i < 4; i++) {
                uint4 bb = sW[(kitg * 8 + nc2_0 + i) * 32 + lane];
                #pragma unroll
                for (int s = 0; s < 2; s++) {
                    mma_bf16(acc[s][2 * i],
                             a[s][0], a[s][1], a[s][2], a[s][3], bb.x, bb.y);
                    mma_bf16(acc[s][2 * i + 1],
                             a[s][0], a[s][1], a[s][2], a[s][3], bb.z, bb.w);
                }
            }
        }

        __syncthreads();   // (B) all reads of sA[buf] done -> reuse as C stage
        uint8_t* sC = (uint8_t*)(smem + GM_SA_OFF + buf * GM_SA_BYTES);

        // write e4m3 C fragments: thread owns cols (qc*2, qc*2+1) in each nt tile
        #pragma unroll
        for (int s = 0; s < 2; s++) {
            int r0 = mrow + s * 16 + qr;
            #pragma unroll
            for (int nt = 0; nt < 8; nt++) {
                int col = ncol + nt * 8 + qc * 2;
                *(uint16_t*)&sC[r0 * 128 + col] =
                    pk_e4m3x2(acc[s][nt][0], acc[s][nt][1]);
                *(uint16_t*)&sC[(r0 + 8) * 128 + col] =
                    pk_e4m3x2(acc[s][nt][2], acc[s][nt][3]);
            }
        }
        __syncthreads();   // (C) C tile complete

        // coalesced copy-out: 16KB, 16B per thread x 4
        #pragma unroll
        for (int k = 0; k < 4; k++) {
            int idx = tid + k * 256;
            int r = idx >> 3;
            int gr = row0 + r;
            if (gr < n) {
                uint4 v = *(const uint4*)&sC[idx * 16];
                *(uint4*)&tout[(size_t)gr * D + (idx & 7) * 16] = v;
            }
        }
        __syncthreads();   // (D) copy-out done before next prefetch reuses buffer
        buf ^= 1;
    }
}

// ================= aggregation: full warp per node, fp8 gathers ===================
// Row = 128 e4m3 = 128B. Lane16 owns 8 cols (8B load); halves process different
// 8-edge windows of the SAME node (no pairing imbalance). f16x2 accumulation,
// cross-half shfl reduce, lanes 0-15 emit bf16 (pre-scaled by inv_out).
__global__ void __launch_bounds__(256)
k_agg(const uint8_t* __restrict__ tin, const float* __restrict__ bias,
      __nv_bfloat16* __restrict__ hbout, int n, int last) {
    __shared__ float sCol[D];
    int tid = threadIdx.x;
    if (last) {
        if (tid < D) sCol[tid] = 0.0f;
        __syncthreads();
    }

    int wnode = (blockIdx.x * blockDim.x + tid) >> 5;   // warp = node
    int lane = tid & 31;
    int lane16 = lane & 15;
    int halfsel = (lane >> 4) * 8;                       // 0 or 8: edge window
    bool active = wnode < n;
    int s = 0, deg = 0;
    if (active) { s = g_row_off[wnode]; deg = g_row_off[wnode + 1] - s; }
    int coff = lane16 * 8;                               // fp8 col offset (8B)

    __half2 acc[4];
    #pragma unroll
    for (int j = 0; j < 4; j++) acc[j] = __half2(__float2half(0.f), __float2half(0.f));

    for (int base = 0; base < deg; base += 16) {
        int m = deg - base;
        if (m > 16) m = 16;
        int idx = 0;
        if (lane16 < m) idx = g_csr[s + base + lane16];

        #pragma unroll
        for (int jb = 0; jb < 8; jb++) {
            int j = halfsel + jb;
            int ij = __shfl_sync(0xffffffffu, idx, j);
            uint2 v = make_uint2(0u, 0u);
            if (j < m) v = *(const uint2*)&tin[(size_t)ij * D + coff];
            uint16_t* p = (uint16_t*)&v;
            acc[0] = __hadd2(acc[0], e4m3x2_h2(p[0]));
            acc[1] = __hadd2(acc[1], e4m3x2_h2(p[1]));
            acc[2] = __hadd2(acc[2], e4m3x2_h2(p[2]));
            acc[3] = __hadd2(acc[3], e4m3x2_h2(p[3]));
        }
    }

    // cross-half reduction (halves hold same cols, different edges)
    #pragma unroll
    for (int j = 0; j < 4; j++) {
        uint32_t u = *(uint32_t*)&acc[j];
        uint32_t o = __shfl_xor_sync(0xffffffffu, u, 16);
        acc[j] = __hadd2(acc[j], *(__half2*)&o);
    }

    if (active && lane < 16) {
        float a[8];
        #pragma unroll
        for (int j = 0; j < 4; j++) {
            float2 f = __half22float2(acc[j]);
            a[2 * j] = f.x; a[2 * j + 1] = f.y;
        }
        float inv = g_inv_in[wnode];
        float o[8];
        #pragma unroll
        for (int j = 0; j < 8; j++)
            o[j] = fmaxf(fmaf(a[j], inv, bias[coff + j]), 0.f);

        if (!last) {
            float so = g_inv_out[wnode];   // pre-scale for next gemm
            uint4 u;
            u.x = pk_bf16x2(o[0] * so, o[1] * so);
            u.y = pk_bf16x2(o[2] * so, o[3] * so);
            u.z = pk_bf16x2(o[4] * so, o[5] * so);
            u.w = pk_bf16x2(o[6] * so, o[7] * so);
            *(uint4*)&hbout[(size_t)wnode * D + coff] = u;
        } else {
            #pragma unroll
            for (int j = 0; j < 8; j++) atomicAdd(&sCol[coff + j], o[j]);
        }
    }

    if (last) {
        __syncthreads();
        if (tid < D) atomicAdd(&g_colsum[tid], sCol[tid]);
    }
}

// ================= epilogue =======================================================
__global__ void k_mlp(const float* __restrict__ Wl1, const float* __restrict__ bl1,
                      const float* __restrict__ Wl2, const float* __restrict__ bl2,
                      const float* __restrict__ Wo,  const float* __restrict__ bo,
                      float* __restrict__ out, int n) {
    __shared__ float s0[D], s1[D], s2[D];
    int t = threadIdx.x;
    s0[t] = g_colsum[t] * (1.0f / (float)n);
    __syncthreads();

    float a = bl1[t];
    for (int k = 0; k < D; k++) a = fmaf(s0[k], Wl1[k * D + t], a);
    s1[t] = fmaxf(a, 0.f);
    __syncthreads();

    float a2 = bl2[t];
    for (int k = 0; k < D; k++) a2 = fmaf(s1[k], Wl2[k * D + t], a2);
    s2[t] = fmaxf(a2, 0.f) * Wo[t];
    __syncthreads();

    for (int off = 64; off > 0; off >>= 1) {
        if (t < off) s2[t] += s2[t + off];
        __syncthreads();
    }
    if (t == 0) out[0] = s2[0] + bo[0];
}

// Tail cleanup: re-zero scratch for the NEXT graph replay.
__global__ void k_clean(int n) {
    int i = blockIdx.x * blockDim.x + threadIdx.x;
    if (i < n) { g_deg_out[i] = 0; g_deg_in[i] = 0; g_cursor[i] = 0; }
    if (i < D) g_colsum[i] = 0.0f;
    if (i < 256) g_bflag[i] = 0;
}

// ================= launch =========================================================
extern "C" void kernel_launch(void* const* d_in, const int* in_sizes, int n_in,
                              void* d_out, int out_size) {
    const float* x   = (const float*)d_in[0];
    const int*   src = (const int*)  d_in[1];
    const int*   dst = (const int*)  d_in[2];
    const float* W1  = (const float*)d_in[3];
    const float* b1  = (const float*)d_in[4];
    const float* W2  = (const float*)d_in[5];
    const float* b2  = (const float*)d_in[6];
    const float* W3  = (const float*)d_in[7];
    const float* b3  = (const float*)d_in[8];
    const float* W4  = (const float*)d_in[9];
    const float* b4  = (const float*)d_in[10];
    const float* Wl1 = (const float*)d_in[11];
    const float* bl1 = (const float*)d_in[12];
    const float* Wl2 = (const float*)d_in[13];
    const float* bl2 = (const float*)d_in[14];
    const float* Wo  = (const float*)d_in[15];
    const float* bo  = (const float*)d_in[16];
    float* out = (float*)d_out;

    int n = in_sizes[0] / D;
    int e = in_sizes[1];

    cudaFuncSetAttribute(k_gemm_mma, cudaFuncAttributeMaxDynamicSharedMemorySize,
                         GM_SMEM);

    __nv_bfloat16* hb;
    uint8_t* t;
    uint4* wf;
    cudaGetSymbolAddress((void**)&hb, g_hb);
    cudaGetSymbolAddress((void**)&t,  g_t);
    cudaGetSymbolAddress((void**)&wf, g_wfrag);

    int nb = (n + SCAN_B - 1) / SCAN_B;
    int ntiles = (n + 127) / 128;
    int ggrid  = ntiles < 296 ? ntiles : 296;
    int agg_grid = (n * 32 + 255) / 256;

    // launch order: gemm layer 1 sits at index 3 (ncu's empirical capture slot)
    k_deg   <<<(e + 255) / 256, 256>>>(src, dst, e);                    // 0
    k_scanf <<<nb, SCAN_B>>>(n);                                        // 1
    k_fillw <<<(e + 255) / 256, 256>>>(src, dst, e, x, n, W1, W2, W3, W4); // 2

    // layer 1
    k_gemm_mma<<<ggrid, 256, GM_SMEM>>>(hb, wf + 0 * 2048, t, n, ntiles); // 3 <- ncu
    k_agg     <<<agg_grid, 256>>>(t, b1, hb, n, 0);
    // layer 2
    k_gemm_mma<<<ggrid, 256, GM_SMEM>>>(hb, wf + 1 * 2048, t, n, ntiles);
    k_agg     <<<agg_grid, 256>>>(t, b2, hb, n, 0);
    // layer 3
    k_gemm_mma<<<ggrid, 256, GM_SMEM>>>(hb, wf + 2 * 2048, t, n, ntiles);
    k_agg     <<<agg_grid, 256>>>(t, b3, hb, n, 0);
    // layer 4 (column-sum only)
    k_gemm_mma<<<ggrid, 256, GM_SMEM>>>(hb, wf + 3 * 2048, t, n, ntiles);
    k_agg     <<<agg_grid, 256>>>(t, b4, hb, n, 1);

    k_mlp  <<<1, D>>>(Wl1, bl1, Wl2, bl2, Wo, bo, out, n);
    k_clean<<<(n + 255) / 256, 256>>>(n);
}